// round 1
// baseline (speedup 1.0000x reference)
#include <cuda_runtime.h>

#define NN     100000
#define F_IN   128
#define F_HID  128
#define F_OUT  64
#define H1     8

// ---------------- scratch (static device globals; no allocs allowed) ----------------
__device__ float g_feat1[NN * F_HID];   // layer1 projected features  [N,8,16]
__device__ float g_el1[NN * H1];
__device__ float g_er1[NN * H1];
__device__ float g_s1 [NN * H1];        // softmax denominators layer1
__device__ float g_h1 [NN * F_HID];     // layer1 output (pre-relu, bias pre-added)
__device__ float g_feat2[NN * F_OUT];   // layer2 projected features
__device__ float g_el2[NN];
__device__ float g_er2[NN];
__device__ float g_s2 [NN];

__device__ __forceinline__ float leaky(float v) { return v > 0.f ? v : 0.2f * v; }

// vectorized no-return global reduction (sm_90+)
__device__ __forceinline__ void red4(float* addr, float4 v) {
    asm volatile("red.global.add.v4.f32 [%0], {%1,%2,%3,%4};"
                 :: "l"(addr), "f"(v.x), "f"(v.y), "f"(v.z), "f"(v.w) : "memory");
}

// ---------------- init: zero denominators, seed outputs with bias ----------------
__global__ void init_kernel(float* __restrict__ out,
                            const float* __restrict__ bias1,
                            const float* __restrict__ bias2) {
    int i = blockIdx.x * blockDim.x + threadIdx.x;
    if (i < NN * F_HID) g_h1[i] = bias1[i & (F_HID - 1)];
    if (i < NN * F_OUT) out[i]  = bias2[i & (F_OUT - 1)];
    if (i < NN * H1)    g_s1[i] = 0.f;
    if (i < NN)         g_s2[i] = 0.f;
}

// ---------------- tiled fp32 SGEMM: C[M,Nd] = A[M,Kd] @ B[Kd,Nd] ----------------
// launched with grid.x = ceil(M/BM); requires Nd == BN.
template<int BM, int BN, int BK, int TM, int TN, bool RELU_IN>
__global__ __launch_bounds__((BM / TM) * (BN / TN))
void sgemm(const float* __restrict__ A, const float* __restrict__ B,
           float* __restrict__ C, int M, int Kd, int Nd) {
    constexpr int NTH = (BM / TM) * (BN / TN);
    __shared__ float As[BK][BM];
    __shared__ float Bs[BK][BN];
    const int tid = threadIdx.x;
    const int tx = tid % (BN / TN);
    const int ty = tid / (BN / TN);
    const int rowBase = blockIdx.x * BM;

    float acc[TM][TN];
#pragma unroll
    for (int i = 0; i < TM; i++)
#pragma unroll
        for (int j = 0; j < TN; j++) acc[i][j] = 0.f;

    for (int k0 = 0; k0 < Kd; k0 += BK) {
        for (int i = tid; i < BM * BK / 4; i += NTH) {
            int r  = i / (BK / 4);
            int c4 = (i % (BK / 4)) * 4;
            int grow = rowBase + r;
            float4 v = make_float4(0.f, 0.f, 0.f, 0.f);
            if (grow < M)
                v = *reinterpret_cast<const float4*>(A + (size_t)grow * Kd + k0 + c4);
            if (RELU_IN) {
                v.x = fmaxf(v.x, 0.f); v.y = fmaxf(v.y, 0.f);
                v.z = fmaxf(v.z, 0.f); v.w = fmaxf(v.w, 0.f);
            }
            As[c4 + 0][r] = v.x; As[c4 + 1][r] = v.y;
            As[c4 + 2][r] = v.z; As[c4 + 3][r] = v.w;
        }
        for (int i = tid; i < BK * BN / 4; i += NTH) {
            int r  = i / (BN / 4);
            int c4 = (i % (BN / 4)) * 4;
            *reinterpret_cast<float4*>(&Bs[r][c4]) =
                *reinterpret_cast<const float4*>(B + (size_t)(k0 + r) * Nd + c4);
        }
        __syncthreads();
#pragma unroll
        for (int kk = 0; kk < BK; kk++) {
            float a[TM], b[TN];
#pragma unroll
            for (int i = 0; i < TM; i += 4) {
                float4 av = *reinterpret_cast<const float4*>(&As[kk][ty * TM + i]);
                a[i] = av.x; a[i + 1] = av.y; a[i + 2] = av.z; a[i + 3] = av.w;
            }
#pragma unroll
            for (int j = 0; j < TN; j += 4) {
                float4 bv = *reinterpret_cast<const float4*>(&Bs[kk][tx * TN + j]);
                b[j] = bv.x; b[j + 1] = bv.y; b[j + 2] = bv.z; b[j + 3] = bv.w;
            }
#pragma unroll
            for (int i = 0; i < TM; i++)
#pragma unroll
                for (int j = 0; j < TN; j++)
                    acc[i][j] = fmaf(a[i], b[j], acc[i][j]);
        }
        __syncthreads();
    }
#pragma unroll
    for (int i = 0; i < TM; i++) {
        int r = rowBase + ty * TM + i;
        if (r < M) {
#pragma unroll
            for (int j = 0; j < TN; j += 4) {
                float4 v = make_float4(acc[i][j], acc[i][j + 1], acc[i][j + 2], acc[i][j + 3]);
                *reinterpret_cast<float4*>(C + (size_t)r * Nd + tx * TN + j) = v;
            }
        }
    }
}

// ---------------- per-node el/er, layer1: warp per node (8 heads x 16 dims) ----------------
__global__ void elr1_kernel(const float* __restrict__ attn_l, const float* __restrict__ attn_r) {
    int t = blockIdx.x * blockDim.x + threadIdx.x;
    int node = t >> 5;
    if (node >= NN) return;
    int lane = t & 31;
    int h = lane >> 2, q = lane & 3;
    float4 f  = *reinterpret_cast<const float4*>(g_feat1 + (size_t)node * F_HID + lane * 4);
    float4 al = *reinterpret_cast<const float4*>(attn_l + h * 16 + q * 4);
    float4 ar = *reinterpret_cast<const float4*>(attn_r + h * 16 + q * 4);
    float pl = f.x * al.x + f.y * al.y + f.z * al.z + f.w * al.w;
    float pr = f.x * ar.x + f.y * ar.y + f.z * ar.z + f.w * ar.w;
    pl += __shfl_xor_sync(0xffffffffu, pl, 1);
    pl += __shfl_xor_sync(0xffffffffu, pl, 2);
    pr += __shfl_xor_sync(0xffffffffu, pr, 1);
    pr += __shfl_xor_sync(0xffffffffu, pr, 2);
    if (q == 0) { g_el1[node * H1 + h] = pl; g_er1[node * H1 + h] = pr; }
}

// ---------------- per-node el/er, layer2: half-warp per node (1 head x 64 dims) -------------
__global__ void elr2_kernel(const float* __restrict__ attn_l, const float* __restrict__ attn_r) {
    int t = blockIdx.x * blockDim.x + threadIdx.x;
    int lane = t & 31;
    int half = lane >> 4;
    int sub  = lane & 15;
    int node = ((t >> 5) << 1) + half;
    float pl = 0.f, pr = 0.f;
    if (node < NN) {
        float4 f  = *reinterpret_cast<const float4*>(g_feat2 + (size_t)node * F_OUT + sub * 4);
        float4 al = *reinterpret_cast<const float4*>(attn_l + sub * 4);
        float4 ar = *reinterpret_cast<const float4*>(attn_r + sub * 4);
        pl = f.x * al.x + f.y * al.y + f.z * al.z + f.w * al.w;
        pr = f.x * ar.x + f.y * ar.y + f.z * ar.z + f.w * ar.w;
    }
#pragma unroll
    for (int k = 1; k < 16; k <<= 1) {
        pl += __shfl_xor_sync(0xffffffffu, pl, k);
        pr += __shfl_xor_sync(0xffffffffu, pr, k);
    }
    if (sub == 0 && node < NN) { g_el2[node] = pl; g_er2[node] = pr; }
}

// ---------------- layer1 softmax denominator: thread per edge ----------------
__global__ void edge_s1_kernel(const int* __restrict__ src, const int* __restrict__ dst, int E) {
    int e = blockIdx.x * blockDim.x + threadIdx.x;
    if (e >= E) return;
    int s = src[e], d = dst[e];
    float4 a0 = *reinterpret_cast<const float4*>(g_el1 + (size_t)s * H1);
    float4 a1 = *reinterpret_cast<const float4*>(g_el1 + (size_t)s * H1 + 4);
    float4 b0 = *reinterpret_cast<const float4*>(g_er1 + (size_t)d * H1);
    float4 b1 = *reinterpret_cast<const float4*>(g_er1 + (size_t)d * H1 + 4);
    float4 p0, p1;
    p0.x = __expf(leaky(a0.x + b0.x)); p0.y = __expf(leaky(a0.y + b0.y));
    p0.z = __expf(leaky(a0.z + b0.z)); p0.w = __expf(leaky(a0.w + b0.w));
    p1.x = __expf(leaky(a1.x + b1.x)); p1.y = __expf(leaky(a1.y + b1.y));
    p1.z = __expf(leaky(a1.z + b1.z)); p1.w = __expf(leaky(a1.w + b1.w));
    red4(g_s1 + (size_t)d * H1, p0);
    red4(g_s1 + (size_t)d * H1 + 4, p1);
}

// ---------------- layer1 aggregate: warp per edge (128 floats via float4/lane) --------------
__global__ void edge_agg1_kernel(const int* __restrict__ src, const int* __restrict__ dst, int E) {
    int t = blockIdx.x * blockDim.x + threadIdx.x;
    int e = t >> 5;
    if (e >= E) return;
    int lane = t & 31;
    int s = src[e], d = dst[e];
    int h = lane >> 2;
    float el = __ldg(g_el1 + (size_t)s * H1 + h);
    float er = __ldg(g_er1 + (size_t)d * H1 + h);
    float p = __expf(leaky(el + er));
    float sd = __ldg(g_s1 + (size_t)d * H1 + h);
    float a = p / fmaxf(sd, 1e-9f);
    float4 f = *reinterpret_cast<const float4*>(g_feat1 + (size_t)s * F_HID + lane * 4);
    red4(g_h1 + (size_t)d * F_HID + lane * 4, make_float4(a * f.x, a * f.y, a * f.z, a * f.w));
}

// ---------------- layer2 softmax denominator ----------------
__global__ void edge_s2_kernel(const int* __restrict__ src, const int* __restrict__ dst, int E) {
    int e = blockIdx.x * blockDim.x + threadIdx.x;
    if (e >= E) return;
    int s = src[e], d = dst[e];
    float p = __expf(leaky(g_el2[s] + g_er2[d]));
    atomicAdd(&g_s2[d], p);
}

// ---------------- layer2 aggregate: half-warp per edge (64 floats) ----------------
__global__ void edge_agg2_kernel(const int* __restrict__ src, const int* __restrict__ dst,
                                 float* __restrict__ out, int E) {
    int t = blockIdx.x * blockDim.x + threadIdx.x;
    int e = t >> 4;
    if (e >= E) return;
    int sub = t & 15;
    int s = src[e], d = dst[e];
    float p = __expf(leaky(__ldg(g_el2 + s) + __ldg(g_er2 + d)));
    float a = p / fmaxf(__ldg(g_s2 + d), 1e-9f);
    float4 f = *reinterpret_cast<const float4*>(g_feat2 + (size_t)s * F_OUT + sub * 4);
    red4(out + (size_t)d * F_OUT + sub * 4, make_float4(a * f.x, a * f.y, a * f.z, a * f.w));
}

// ---------------- launch ----------------
extern "C" void kernel_launch(void* const* d_in, const int* in_sizes, int n_in,
                              void* d_out, int out_size) {
    const float* x   = (const float*)d_in[0];
    const int*   src = (const int*)  d_in[1];
    const int*   dst = (const int*)  d_in[2];
    const float* W1  = (const float*)d_in[3];
    const float* al1 = (const float*)d_in[4];
    const float* ar1 = (const float*)d_in[5];
    const float* b1  = (const float*)d_in[6];
    const float* W2  = (const float*)d_in[7];
    const float* al2 = (const float*)d_in[8];
    const float* ar2 = (const float*)d_in[9];
    const float* b2  = (const float*)d_in[10];
    float* out = (float*)d_out;
    const int E = in_sizes[1];
    const int M = NN;

    float *feat1, *h1, *feat2;
    cudaGetSymbolAddress((void**)&feat1, g_feat1);
    cudaGetSymbolAddress((void**)&h1,    g_h1);
    cudaGetSymbolAddress((void**)&feat2, g_feat2);

    init_kernel<<<(NN * F_HID + 255) / 256, 256>>>(out, b1, b2);

    // layer 1
    sgemm<128, 128, 16, 8, 8, false><<<(M + 127) / 128, 256>>>(x, W1, feat1, M, F_IN, F_HID);
    elr1_kernel<<<(NN * 32 + 255) / 256, 256>>>(al1, ar1);
    edge_s1_kernel<<<(E + 255) / 256, 256>>>(src, dst, E);
    edge_agg1_kernel<<<(E * 32 + 255) / 256, 256>>>(src, dst, E);

    // layer 2 (relu applied on A-load inside the GEMM)
    sgemm<128, 64, 16, 8, 4, true><<<(M + 127) / 128, 256>>>(h1, W2, feat2, M, F_HID, F_OUT);
    elr2_kernel<<<(((NN + 1) / 2) * 32 + 255) / 256, 256>>>(al2, ar2);
    edge_s2_kernel<<<(E + 255) / 256, 256>>>(src, dst, E);
    edge_agg2_kernel<<<(E * 16 + 255) / 256, 256>>>(src, dst, out, E);
}

// round 2
// speedup vs baseline: 1.1668x; 1.1668x over previous
#include <cuda_runtime.h>

#define NN     100000
#define F_IN   128
#define F_HID  128
#define F_OUT  64
#define H1     8
#define EDGES  1600000

// ---------------- scratch (static device globals; no allocs allowed) ----------------
__device__ float g_feat1[NN * F_HID];   // layer1 projected features  [N,8,16]
__device__ float g_el1[NN * H1];
__device__ float g_er1[NN * H1];
__device__ float g_h1 [NN * F_HID];     // layer1 output (bias added, pre-relu)
__device__ float g_feat2[NN * F_OUT];   // layer2 projected features
__device__ float g_el2[NN];
__device__ float g_er2[NN];
// CSR by dst
__device__ int g_deg[NN];
__device__ int g_off[NN + 1];
__device__ int g_cursor[NN];
__device__ int g_esrc[EDGES];           // src node per edge, bucketed by dst

__device__ __forceinline__ float leaky(float v) { return v > 0.f ? v : 0.2f * v; }

// ---------------- init: zero degree counters ----------------
__global__ void init_kernel() {
    int i = blockIdx.x * blockDim.x + threadIdx.x;
    if (i < NN) g_deg[i] = 0;
}

// ---------------- CSR build ----------------
__global__ void hist_kernel(const int* __restrict__ dst, int E) {
    int e = blockIdx.x * blockDim.x + threadIdx.x;
    if (e < E) atomicAdd(&g_deg[dst[e]], 1);
}

// single-block exclusive scan of g_deg -> g_off, g_cursor
__global__ void scan_kernel(int E) {
    __shared__ int partials[1024];
    const int CH = (NN + 1023) / 1024;   // 98
    int t = threadIdx.x;
    int base = t * CH;
    int lim = min(base + CH, NN);
    int sum = 0;
    for (int i = base; i < lim; i++) sum += g_deg[i];
    partials[t] = sum;
    __syncthreads();
    for (int ofs = 1; ofs < 1024; ofs <<= 1) {
        int v = (t >= ofs) ? partials[t - ofs] : 0;
        __syncthreads();
        partials[t] += v;
        __syncthreads();
    }
    int run = partials[t] - sum;         // exclusive base for this chunk
    for (int i = base; i < lim; i++) {
        g_off[i] = run;
        g_cursor[i] = run;
        run += g_deg[i];
    }
    if (base <= NN && base + CH > NN) g_off[NN] = E;
}

__global__ void scatter_kernel(const int* __restrict__ src, const int* __restrict__ dst, int E) {
    int e = blockIdx.x * blockDim.x + threadIdx.x;
    if (e >= E) return;
    int d = dst[e];
    int pos = atomicAdd(&g_cursor[d], 1);
    g_esrc[pos] = src[e];
}

// ---------------- tiled fp32 SGEMM: C[M,Nd] = A[M,Kd] @ B[Kd,Nd] ----------------
template<int BM, int BN, int BK, int TM, int TN, bool RELU_IN>
__global__ __launch_bounds__((BM / TM) * (BN / TN))
void sgemm(const float* __restrict__ A, const float* __restrict__ B,
           float* __restrict__ C, int M, int Kd, int Nd) {
    constexpr int NTH = (BM / TM) * (BN / TN);
    __shared__ float As[BK][BM];
    __shared__ float Bs[BK][BN];
    const int tid = threadIdx.x;
    const int tx = tid % (BN / TN);
    const int ty = tid / (BN / TN);
    const int rowBase = blockIdx.x * BM;

    float acc[TM][TN];
#pragma unroll
    for (int i = 0; i < TM; i++)
#pragma unroll
        for (int j = 0; j < TN; j++) acc[i][j] = 0.f;

    for (int k0 = 0; k0 < Kd; k0 += BK) {
        for (int i = tid; i < BM * BK / 4; i += NTH) {
            int r  = i / (BK / 4);
            int c4 = (i % (BK / 4)) * 4;
            int grow = rowBase + r;
            float4 v = make_float4(0.f, 0.f, 0.f, 0.f);
            if (grow < M)
                v = *reinterpret_cast<const float4*>(A + (size_t)grow * Kd + k0 + c4);
            if (RELU_IN) {
                v.x = fmaxf(v.x, 0.f); v.y = fmaxf(v.y, 0.f);
                v.z = fmaxf(v.z, 0.f); v.w = fmaxf(v.w, 0.f);
            }
            As[c4 + 0][r] = v.x; As[c4 + 1][r] = v.y;
            As[c4 + 2][r] = v.z; As[c4 + 3][r] = v.w;
        }
        for (int i = tid; i < BK * BN / 4; i += NTH) {
            int r  = i / (BN / 4);
            int c4 = (i % (BN / 4)) * 4;
            *reinterpret_cast<float4*>(&Bs[r][c4]) =
                *reinterpret_cast<const float4*>(B + (size_t)(k0 + r) * Nd + c4);
        }
        __syncthreads();
#pragma unroll
        for (int kk = 0; kk < BK; kk++) {
            float a[TM], b[TN];
#pragma unroll
            for (int i = 0; i < TM; i += 4) {
                float4 av = *reinterpret_cast<const float4*>(&As[kk][ty * TM + i]);
                a[i] = av.x; a[i + 1] = av.y; a[i + 2] = av.z; a[i + 3] = av.w;
            }
#pragma unroll
            for (int j = 0; j < TN; j += 4) {
                float4 bv = *reinterpret_cast<const float4*>(&Bs[kk][tx * TN + j]);
                b[j] = bv.x; b[j + 1] = bv.y; b[j + 2] = bv.z; b[j + 3] = bv.w;
            }
#pragma unroll
            for (int i = 0; i < TM; i++)
#pragma unroll
                for (int j = 0; j < TN; j++)
                    acc[i][j] = fmaf(a[i], b[j], acc[i][j]);
        }
        __syncthreads();
    }
#pragma unroll
    for (int i = 0; i < TM; i++) {
        int r = rowBase + ty * TM + i;
        if (r < M) {
#pragma unroll
            for (int j = 0; j < TN; j += 4) {
                float4 v = make_float4(acc[i][j], acc[i][j + 1], acc[i][j + 2], acc[i][j + 3]);
                *reinterpret_cast<float4*>(C + (size_t)r * Nd + tx * TN + j) = v;
            }
        }
    }
}

// ---------------- per-node el/er, layer1: warp per node (8 heads x 16 dims) ----------------
__global__ void elr1_kernel(const float* __restrict__ attn_l, const float* __restrict__ attn_r) {
    int t = blockIdx.x * blockDim.x + threadIdx.x;
    int node = t >> 5;
    if (node >= NN) return;
    int lane = t & 31;
    int h = lane >> 2, q = lane & 3;
    float4 f  = *reinterpret_cast<const float4*>(g_feat1 + (size_t)node * F_HID + lane * 4);
    float4 al = *reinterpret_cast<const float4*>(attn_l + h * 16 + q * 4);
    float4 ar = *reinterpret_cast<const float4*>(attn_r + h * 16 + q * 4);
    float pl = f.x * al.x + f.y * al.y + f.z * al.z + f.w * al.w;
    float pr = f.x * ar.x + f.y * ar.y + f.z * ar.z + f.w * ar.w;
    pl += __shfl_xor_sync(0xffffffffu, pl, 1);
    pl += __shfl_xor_sync(0xffffffffu, pl, 2);
    pr += __shfl_xor_sync(0xffffffffu, pr, 1);
    pr += __shfl_xor_sync(0xffffffffu, pr, 2);
    if (q == 0) { g_el1[node * H1 + h] = pl; g_er1[node * H1 + h] = pr; }
}

// ---------------- per-node el/er, layer2: half-warp per node (1 head x 64 dims) -------------
__global__ void elr2_kernel(const float* __restrict__ attn_l, const float* __restrict__ attn_r) {
    int t = blockIdx.x * blockDim.x + threadIdx.x;
    int lane = t & 31;
    int half = lane >> 4;
    int sub  = lane & 15;
    int node = ((t >> 5) << 1) + half;
    float pl = 0.f, pr = 0.f;
    if (node < NN) {
        float4 f  = *reinterpret_cast<const float4*>(g_feat2 + (size_t)node * F_OUT + sub * 4);
        float4 al = *reinterpret_cast<const float4*>(attn_l + sub * 4);
        float4 ar = *reinterpret_cast<const float4*>(attn_r + sub * 4);
        pl = f.x * al.x + f.y * al.y + f.z * al.z + f.w * al.w;
        pr = f.x * ar.x + f.y * ar.y + f.z * ar.z + f.w * ar.w;
    }
#pragma unroll
    for (int k = 1; k < 16; k <<= 1) {
        pl += __shfl_xor_sync(0xffffffffu, pl, k);
        pr += __shfl_xor_sync(0xffffffffu, pr, k);
    }
    if (sub == 0 && node < NN) { g_el2[node] = pl; g_er2[node] = pr; }
}

// ---------------- layer1 fused softmax+aggregate: warp per dst node ----------------
// lane -> (h = lane>>2, 4 consecutive feature floats at lane*4)
// p-duty lanes: lane -> edge (lane>>3) within group of 4, head (lane&7)
__global__ void agg1_kernel(const float* __restrict__ bias1) {
    int t = blockIdx.x * blockDim.x + threadIdx.x;
    int w = t >> 5;
    if (w >= NN) return;
    int lane = t & 31;
    int h = lane >> 2;

    int beg = g_off[w], end = g_off[w + 1];
    float er_acc = __ldg(g_er1 + (size_t)w * H1 + h);          // for accumulation role
    float er_p   = __ldg(g_er1 + (size_t)w * H1 + (lane & 7)); // for p-duty role

    float acc0 = 0.f, acc1 = 0.f, acc2 = 0.f, acc3 = 0.f, ssum = 0.f;

    for (int i0 = beg; i0 < end; i0 += 32) {
        int n = end - i0; if (n > 32) n = 32;
        int sreg = (lane < n) ? __ldg(g_esrc + i0 + lane) : 0;
        for (int jb = 0; jb < n; jb += 4) {
            // p-duty: edge jb + (lane>>3), head (lane&7)
            int sj = __shfl_sync(0xffffffffu, sreg, jb + (lane >> 3));
            float pm = __expf(leaky(__ldg(g_el1 + (size_t)sj * H1 + (lane & 7)) + er_p));
            int jlim = n - jb; if (jlim > 4) jlim = 4;
#pragma unroll
            for (int j2 = 0; j2 < 4; j2++) {
                if (j2 >= jlim) break;
                int s = __shfl_sync(0xffffffffu, sreg, jb + j2);
                float p = __shfl_sync(0xffffffffu, pm, (j2 << 3) | h);
                float4 f = *reinterpret_cast<const float4*>(g_feat1 + (size_t)s * F_HID + lane * 4);
                acc0 = fmaf(p, f.x, acc0);
                acc1 = fmaf(p, f.y, acc1);
                acc2 = fmaf(p, f.z, acc2);
                acc3 = fmaf(p, f.w, acc3);
                ssum += p;
            }
        }
    }
    float inv = 1.f / fmaxf(ssum, 1e-9f);
    float4 b = *reinterpret_cast<const float4*>(bias1 + lane * 4);
    float4 o = make_float4(acc0 * inv + b.x, acc1 * inv + b.y,
                           acc2 * inv + b.z, acc3 * inv + b.w);
    *reinterpret_cast<float4*>(g_h1 + (size_t)w * F_HID + lane * 4) = o;
}

// ---------------- layer2 fused softmax+aggregate: warp per dst node (64 floats) -------------
__global__ void agg2_kernel(const float* __restrict__ bias2, float* __restrict__ out) {
    int t = blockIdx.x * blockDim.x + threadIdx.x;
    int w = t >> 5;
    if (w >= NN) return;
    int lane = t & 31;

    int beg = g_off[w], end = g_off[w + 1];
    float er = __ldg(g_er2 + w);

    float acc0 = 0.f, acc1 = 0.f, ssum = 0.f;

    for (int i0 = beg; i0 < end; i0 += 32) {
        int n = end - i0; if (n > 32) n = 32;
        int sreg = (lane < n) ? __ldg(g_esrc + i0 + lane) : 0;
        float pl = __expf(leaky(__ldg(g_el2 + sreg) + er));  // p for edge i0+lane
        for (int j = 0; j < n; j++) {
            int s   = __shfl_sync(0xffffffffu, sreg, j);
            float p = __shfl_sync(0xffffffffu, pl, j);
            float2 f = *reinterpret_cast<const float2*>(g_feat2 + (size_t)s * F_OUT + lane * 2);
            acc0 = fmaf(p, f.x, acc0);
            acc1 = fmaf(p, f.y, acc1);
            ssum += p;
        }
    }
    float inv = 1.f / fmaxf(ssum, 1e-9f);
    float2 b = *reinterpret_cast<const float2*>(bias2 + lane * 2);
    float2 o = make_float2(acc0 * inv + b.x, acc1 * inv + b.y);
    *reinterpret_cast<float2*>(out + (size_t)w * F_OUT + lane * 2) = o;
}

// ---------------- launch ----------------
extern "C" void kernel_launch(void* const* d_in, const int* in_sizes, int n_in,
                              void* d_out, int out_size) {
    const float* x   = (const float*)d_in[0];
    const int*   src = (const int*)  d_in[1];
    const int*   dst = (const int*)  d_in[2];
    const float* W1  = (const float*)d_in[3];
    const float* al1 = (const float*)d_in[4];
    const float* ar1 = (const float*)d_in[5];
    const float* b1  = (const float*)d_in[6];
    const float* W2  = (const float*)d_in[7];
    const float* al2 = (const float*)d_in[8];
    const float* ar2 = (const float*)d_in[9];
    const float* b2  = (const float*)d_in[10];
    float* out = (float*)d_out;
    const int E = in_sizes[1];
    const int M = NN;

    float *feat1, *h1, *feat2;
    cudaGetSymbolAddress((void**)&feat1, g_feat1);
    cudaGetSymbolAddress((void**)&h1,    g_h1);
    cudaGetSymbolAddress((void**)&feat2, g_feat2);

    // CSR build (shared by both layers)
    init_kernel<<<(NN + 255) / 256, 256>>>();
    hist_kernel<<<(E + 255) / 256, 256>>>(dst, E);
    scan_kernel<<<1, 1024>>>(E);
    scatter_kernel<<<(E + 255) / 256, 256>>>(src, dst, E);

    // layer 1
    sgemm<128, 128, 16, 8, 8, false><<<(M + 127) / 128, 256>>>(x, W1, feat1, M, F_IN, F_HID);
    elr1_kernel<<<(NN * 32 + 255) / 256, 256>>>(al1, ar1);
    agg1_kernel<<<(NN * 32 + 255) / 256, 256>>>(b1);

    // layer 2 (relu applied on A-load inside the GEMM)
    sgemm<128, 64, 16, 8, 4, true><<<(M + 127) / 128, 256>>>(h1, W2, feat2, M, F_HID, F_OUT);
    elr2_kernel<<<(((NN + 1) / 2) * 32 + 255) / 256, 256>>>(al2, ar2);
    agg2_kernel<<<(NN * 32 + 255) / 256, 256>>>(b2, out);
}

// round 3
// speedup vs baseline: 1.2750x; 1.0927x over previous
#include <cuda_runtime.h>

#define NN     100000
#define F_IN   128
#define F_HID  128
#define F_OUT  64
#define H1     8
#define EDGES  1600000

// ---------------- scratch (static device globals; no allocs allowed) ----------------
__device__ float g_feat1[NN * F_HID];   // layer1 projected features  [N,8,16]
__device__ float g_el1[NN * H1];
__device__ float g_er1[NN * H1];
__device__ float g_h1 [NN * F_HID];     // layer1 output (bias added, pre-relu)
__device__ float g_feat2[NN * F_OUT];   // layer2 projected features
__device__ float g_el2[NN];
__device__ float g_er2[NN];
// CSR by dst
__device__ int g_deg[NN];
__device__ int g_off[NN + 1];
__device__ int g_cursor[NN];
__device__ int g_esrc[EDGES];           // src node per edge, bucketed by dst

__device__ __forceinline__ float leaky(float v) { return v > 0.f ? v : 0.2f * v; }

// ---------------- init: zero degree counters ----------------
__global__ void init_kernel() {
    int i = blockIdx.x * blockDim.x + threadIdx.x;
    if (i < NN) g_deg[i] = 0;
}

// ---------------- CSR build ----------------
__global__ void hist_kernel(const int* __restrict__ dst, int E) {
    int e = blockIdx.x * blockDim.x + threadIdx.x;
    if (e < E) atomicAdd(&g_deg[dst[e]], 1);
}

// single-block exclusive scan of g_deg -> g_off, g_cursor
__global__ void scan_kernel(int E) {
    __shared__ int partials[1024];
    const int CH = (NN + 1023) / 1024;   // 98
    int t = threadIdx.x;
    int base = t * CH;
    int lim = min(base + CH, NN);
    int sum = 0;
    for (int i = base; i < lim; i++) sum += g_deg[i];
    partials[t] = sum;
    __syncthreads();
    for (int ofs = 1; ofs < 1024; ofs <<= 1) {
        int v = (t >= ofs) ? partials[t - ofs] : 0;
        __syncthreads();
        partials[t] += v;
        __syncthreads();
    }
    int run = partials[t] - sum;         // exclusive base for this chunk
    for (int i = base; i < lim; i++) {
        g_off[i] = run;
        g_cursor[i] = run;
        run += g_deg[i];
    }
    if (base <= NN && base + CH > NN) g_off[NN] = E;
}

__global__ void scatter_kernel(const int* __restrict__ src, const int* __restrict__ dst, int E) {
    int e = blockIdx.x * blockDim.x + threadIdx.x;
    if (e >= E) return;
    int d = dst[e];
    int pos = atomicAdd(&g_cursor[d], 1);
    g_esrc[pos] = src[e];
}

// ---------------- double-buffered fp32 SGEMM: C[M,Nd] = A[M,Kd] @ B[Kd,Nd] ----------------
template<int BM, int BN, int BK, int TM, int TN, bool RELU_IN>
__global__ __launch_bounds__((BM / TM) * (BN / TN))
void sgemm(const float* __restrict__ A, const float* __restrict__ B,
           float* __restrict__ C, int M, int Kd, int Nd) {
    constexpr int NTH = (BM / TM) * (BN / TN);
    constexpr int LA = (BM * BK / 4) / NTH;
    constexpr int LB = (BK * BN / 4) / NTH;
    __shared__ float As[2][BK][BM];
    __shared__ float Bs[2][BK][BN];
    const int tid = threadIdx.x;
    const int tx = tid % (BN / TN);
    const int ty = tid / (BN / TN);
    const int rowBase = blockIdx.x * BM;

    float4 pa[LA], pb[LB];
    float acc[TM][TN];
#pragma unroll
    for (int i = 0; i < TM; i++)
#pragma unroll
        for (int j = 0; j < TN; j++) acc[i][j] = 0.f;

    auto ldA = [&](int k0) {
#pragma unroll
        for (int l = 0; l < LA; l++) {
            int i = tid + l * NTH;
            int r = i / (BK / 4), c4 = (i % (BK / 4)) * 4;
            int grow = rowBase + r;
            float4 v = make_float4(0.f, 0.f, 0.f, 0.f);
            if (grow < M) v = *reinterpret_cast<const float4*>(A + (size_t)grow * Kd + k0 + c4);
            if (RELU_IN) {
                v.x = fmaxf(v.x, 0.f); v.y = fmaxf(v.y, 0.f);
                v.z = fmaxf(v.z, 0.f); v.w = fmaxf(v.w, 0.f);
            }
            pa[l] = v;
        }
    };
    auto ldB = [&](int k0) {
#pragma unroll
        for (int l = 0; l < LB; l++) {
            int i = tid + l * NTH;
            int r = i / (BN / 4), c4 = (i % (BN / 4)) * 4;
            pb[l] = *reinterpret_cast<const float4*>(B + (size_t)(k0 + r) * Nd + c4);
        }
    };
    auto stAB = [&](int buf) {
#pragma unroll
        for (int l = 0; l < LA; l++) {
            int i = tid + l * NTH;
            int r = i / (BK / 4), c4 = (i % (BK / 4)) * 4;
            As[buf][c4 + 0][r] = pa[l].x; As[buf][c4 + 1][r] = pa[l].y;
            As[buf][c4 + 2][r] = pa[l].z; As[buf][c4 + 3][r] = pa[l].w;
        }
#pragma unroll
        for (int l = 0; l < LB; l++) {
            int i = tid + l * NTH;
            int r = i / (BN / 4), c4 = (i % (BN / 4)) * 4;
            *reinterpret_cast<float4*>(&Bs[buf][r][c4]) = pb[l];
        }
    };

    ldA(0); ldB(0); stAB(0);
    __syncthreads();
    const int KT = Kd / BK;
    for (int kt = 0; kt < KT; kt++) {
        int cur = kt & 1;
        if (kt + 1 < KT) { ldA((kt + 1) * BK); ldB((kt + 1) * BK); }
#pragma unroll
        for (int kk = 0; kk < BK; kk++) {
            float a[TM], b[TN];
#pragma unroll
            for (int i = 0; i < TM; i += 4) {
                float4 av = *reinterpret_cast<const float4*>(&As[cur][kk][ty * TM + i]);
                a[i] = av.x; a[i + 1] = av.y; a[i + 2] = av.z; a[i + 3] = av.w;
            }
#pragma unroll
            for (int j = 0; j < TN; j += 4) {
                float4 bv = *reinterpret_cast<const float4*>(&Bs[cur][kk][tx * TN + j]);
                b[j] = bv.x; b[j + 1] = bv.y; b[j + 2] = bv.z; b[j + 3] = bv.w;
            }
#pragma unroll
            for (int i = 0; i < TM; i++)
#pragma unroll
                for (int j = 0; j < TN; j++)
                    acc[i][j] = fmaf(a[i], b[j], acc[i][j]);
        }
        if (kt + 1 < KT) { stAB(cur ^ 1); __syncthreads(); }
    }
#pragma unroll
    for (int i = 0; i < TM; i++) {
        int r = rowBase + ty * TM + i;
        if (r < M) {
#pragma unroll
            for (int j = 0; j < TN; j += 4) {
                float4 v = make_float4(acc[i][j], acc[i][j + 1], acc[i][j + 2], acc[i][j + 3]);
                *reinterpret_cast<float4*>(C + (size_t)r * Nd + tx * TN + j) = v;
            }
        }
    }
}

// ---------------- per-node el/er, layer1: warp per node (8 heads x 16 dims) ----------------
__global__ void elr1_kernel(const float* __restrict__ attn_l, const float* __restrict__ attn_r) {
    int t = blockIdx.x * blockDim.x + threadIdx.x;
    int node = t >> 5;
    if (node >= NN) return;
    int lane = t & 31;
    int h = lane >> 2, q = lane & 3;
    float4 f  = *reinterpret_cast<const float4*>(g_feat1 + (size_t)node * F_HID + lane * 4);
    float4 al = *reinterpret_cast<const float4*>(attn_l + h * 16 + q * 4);
    float4 ar = *reinterpret_cast<const float4*>(attn_r + h * 16 + q * 4);
    float pl = f.x * al.x + f.y * al.y + f.z * al.z + f.w * al.w;
    float pr = f.x * ar.x + f.y * ar.y + f.z * ar.z + f.w * ar.w;
    pl += __shfl_xor_sync(0xffffffffu, pl, 1);
    pl += __shfl_xor_sync(0xffffffffu, pl, 2);
    pr += __shfl_xor_sync(0xffffffffu, pr, 1);
    pr += __shfl_xor_sync(0xffffffffu, pr, 2);
    if (q == 0) { g_el1[node * H1 + h] = pl; g_er1[node * H1 + h] = pr; }
}

// ---------------- per-node el/er, layer2: half-warp per node (1 head x 64 dims) -------------
__global__ void elr2_kernel(const float* __restrict__ attn_l, const float* __restrict__ attn_r) {
    int t = blockIdx.x * blockDim.x + threadIdx.x;
    int lane = t & 31;
    int half = lane >> 4;
    int sub  = lane & 15;
    int node = ((t >> 5) << 1) + half;
    float pl = 0.f, pr = 0.f;
    if (node < NN) {
        float4 f  = *reinterpret_cast<const float4*>(g_feat2 + (size_t)node * F_OUT + sub * 4);
        float4 al = *reinterpret_cast<const float4*>(attn_l + sub * 4);
        float4 ar = *reinterpret_cast<const float4*>(attn_r + sub * 4);
        pl = f.x * al.x + f.y * al.y + f.z * al.z + f.w * al.w;
        pr = f.x * ar.x + f.y * ar.y + f.z * ar.z + f.w * ar.w;
    }
#pragma unroll
    for (int k = 1; k < 16; k <<= 1) {
        pl += __shfl_xor_sync(0xffffffffu, pl, k);
        pr += __shfl_xor_sync(0xffffffffu, pr, k);
    }
    if (sub == 0 && node < NN) { g_el2[node] = pl; g_er2[node] = pr; }
}

// ---------------- layer1 fused softmax+aggregate: warp per dst node ----------------
__global__ void agg1_kernel(const float* __restrict__ bias1) {
    int t = blockIdx.x * blockDim.x + threadIdx.x;
    int w = t >> 5;
    if (w >= NN) return;
    int lane = t & 31;
    int h = lane >> 2;

    int beg = g_off[w], end = g_off[w + 1];
    float er_p = __ldg(g_er1 + (size_t)w * H1 + (lane & 7)); // p-duty role head

    float acc0 = 0.f, acc1 = 0.f, acc2 = 0.f, acc3 = 0.f, ssum = 0.f;

    for (int i0 = beg; i0 < end; i0 += 32) {
        int n = end - i0; if (n > 32) n = 32;
        int sreg = __ldg(g_esrc + i0 + min(lane, n - 1));
        for (int jb = 0; jb < n; jb += 4) {
            // p-duty: edge jb + (lane>>3), head (lane&7)
            int je = jb + (lane >> 3); if (je > n - 1) je = n - 1;
            int sj = __shfl_sync(0xffffffffu, sreg, je);
            float pm = __expf(leaky(__ldg(g_el1 + (size_t)sj * H1 + (lane & 7)) + er_p));
#pragma unroll
            for (int j2 = 0; j2 < 4; j2++) {
                int j = jb + j2;
                int s = __shfl_sync(0xffffffffu, sreg, j < 32 ? j : 31);
                float p = __shfl_sync(0xffffffffu, pm, (j2 << 3) | h);
                if (j < n) {
                    float4 f = *reinterpret_cast<const float4*>(g_feat1 + (size_t)s * F_HID + lane * 4);
                    acc0 = fmaf(p, f.x, acc0);
                    acc1 = fmaf(p, f.y, acc1);
                    acc2 = fmaf(p, f.z, acc2);
                    acc3 = fmaf(p, f.w, acc3);
                    ssum += p;
                }
            }
        }
    }
    float inv = 1.f / fmaxf(ssum, 1e-9f);
    float4 b = *reinterpret_cast<const float4*>(bias1 + lane * 4);
    float4 o = make_float4(acc0 * inv + b.x, acc1 * inv + b.y,
                           acc2 * inv + b.z, acc3 * inv + b.w);
    *reinterpret_cast<float4*>(g_h1 + (size_t)w * F_HID + lane * 4) = o;
}

// ---------------- layer2 fused softmax+aggregate: warp per dst node (64 floats) -------------
__global__ void agg2_kernel(const float* __restrict__ bias2, float* __restrict__ out) {
    int t = blockIdx.x * blockDim.x + threadIdx.x;
    int w = t >> 5;
    if (w >= NN) return;
    int lane = t & 31;

    int beg = g_off[w], end = g_off[w + 1];
    float er = __ldg(g_er2 + w);

    float acc0 = 0.f, acc1 = 0.f, ssum = 0.f;

    for (int i0 = beg; i0 < end; i0 += 32) {
        int n = end - i0; if (n > 32) n = 32;
        int sreg = __ldg(g_esrc + i0 + min(lane, n - 1));
        float pl = __expf(leaky(__ldg(g_el2 + sreg) + er));  // p for edge i0+lane
        for (int jb = 0; jb < n; jb += 4) {
#pragma unroll
            for (int j2 = 0; j2 < 4; j2++) {
                int j = jb + j2;
                int jc = j < 32 ? j : 31;
                int s   = __shfl_sync(0xffffffffu, sreg, jc);
                float p = __shfl_sync(0xffffffffu, pl, jc);
                if (j < n) {
                    float2 f = *reinterpret_cast<const float2*>(g_feat2 + (size_t)s * F_OUT + lane * 2);
                    acc0 = fmaf(p, f.x, acc0);
                    acc1 = fmaf(p, f.y, acc1);
                    ssum += p;
                }
            }
        }
    }
    float inv = 1.f / fmaxf(ssum, 1e-9f);
    float2 b = *reinterpret_cast<const float2*>(bias2 + lane * 2);
    float2 o = make_float2(acc0 * inv + b.x, acc1 * inv + b.y);
    *reinterpret_cast<float2*>(out + (size_t)w * F_OUT + lane * 2) = o;
}

// ---------------- launch ----------------
extern "C" void kernel_launch(void* const* d_in, const int* in_sizes, int n_in,
                              void* d_out, int out_size) {
    const float* x   = (const float*)d_in[0];
    const int*   src = (const int*)  d_in[1];
    const int*   dst = (const int*)  d_in[2];
    const float* W1  = (const float*)d_in[3];
    const float* al1 = (const float*)d_in[4];
    const float* ar1 = (const float*)d_in[5];
    const float* b1  = (const float*)d_in[6];
    const float* W2  = (const float*)d_in[7];
    const float* al2 = (const float*)d_in[8];
    const float* ar2 = (const float*)d_in[9];
    const float* b2  = (const float*)d_in[10];
    float* out = (float*)d_out;
    const int E = in_sizes[1];
    const int M = NN;

    float *feat1, *h1, *feat2;
    cudaGetSymbolAddress((void**)&feat1, g_feat1);
    cudaGetSymbolAddress((void**)&h1,    g_h1);
    cudaGetSymbolAddress((void**)&feat2, g_feat2);

    // side stream + fork/join events (host objects, created once; no device mem)
    static cudaStream_t s_side = nullptr;
    static cudaEvent_t  s_fork = nullptr, s_join = nullptr;
    if (!s_side) {
        cudaStreamCreateWithFlags(&s_side, cudaStreamNonBlocking);
        cudaEventCreateWithFlags(&s_fork, cudaEventDisableTiming);
        cudaEventCreateWithFlags(&s_join, cudaEventDisableTiming);
    }

    // fork: CSR build on side stream, concurrent with layer-1 GEMM + elr1
    cudaEventRecord(s_fork, 0);
    cudaStreamWaitEvent(s_side, s_fork, 0);
    init_kernel<<<(NN + 255) / 256, 256, 0, s_side>>>();
    hist_kernel<<<(E + 255) / 256, 256, 0, s_side>>>(dst, E);
    scan_kernel<<<1, 1024, 0, s_side>>>(E);
    scatter_kernel<<<(E + 255) / 256, 256, 0, s_side>>>(src, dst, E);
    cudaEventRecord(s_join, s_side);

    // main stream: layer-1 dense work
    sgemm<128, 128, 16, 8, 8, false><<<(M + 127) / 128, 256>>>(x, W1, feat1, M, F_IN, F_HID);
    elr1_kernel<<<(NN * 32 + 255) / 256, 256>>>(al1, ar1);

    // join: aggregation needs CSR
    cudaStreamWaitEvent(0, s_join, 0);
    agg1_kernel<<<(NN * 32 + 255) / 256, 256>>>(b1);

    // layer 2 (relu applied on A-load inside the GEMM)
    sgemm<128, 64, 16, 8, 4, true><<<(M + 127) / 128, 256>>>(h1, W2, feat2, M, F_HID, F_OUT);
    elr2_kernel<<<(((NN + 1) / 2) * 32 + 255) / 256, 256>>>(al2, ar2);
    agg2_kernel<<<(NN * 32 + 255) / 256, 256>>>(b2, out);
}

// round 4
// speedup vs baseline: 1.3269x; 1.0407x over previous
#include <cuda_runtime.h>
#include <cuda_fp16.h>

#define NN     100000
#define F_IN   128
#define F_HID  128
#define F_OUT  64
#define H1     8
#define EDGES  1600000

// ---------------- scratch (static device globals; no allocs allowed) ----------------
__device__ float  g_feat1[NN * F_HID];   // layer1 projected features (fp32, for elr)
__device__ __half g_feat1h[NN * F_HID];  // fp16 mirror for gather
__device__ float  g_el1[NN * H1];
__device__ float  g_er1[NN * H1];
__device__ float  g_h1 [NN * F_HID];     // layer1 output (bias added, pre-relu)
__device__ float  g_feat2[NN * F_OUT];   // layer2 projected features
__device__ __half g_feat2h[NN * F_OUT];  // fp16 mirror for gather
__device__ float  g_el2[NN];
__device__ float  g_er2[NN];
// CSR by dst
__device__ int g_deg[NN];
__device__ int g_off[NN + 1];
__device__ int g_cursor[NN];
__device__ int g_esrc[EDGES];            // src node per edge, bucketed by dst

__device__ __forceinline__ float leaky(float v) { return v > 0.f ? v : 0.2f * v; }

// ---------------- init: zero degree counters ----------------
__global__ void init_kernel() {
    int i = blockIdx.x * blockDim.x + threadIdx.x;
    if (i < NN) g_deg[i] = 0;
}

// ---------------- CSR build ----------------
__global__ void hist_kernel(const int* __restrict__ dst, int E) {
    int e = blockIdx.x * blockDim.x + threadIdx.x;
    if (e < E) atomicAdd(&g_deg[dst[e]], 1);
}

__global__ void scan_kernel(int E) {
    __shared__ int partials[1024];
    const int CH = (NN + 1023) / 1024;   // 98
    int t = threadIdx.x;
    int base = t * CH;
    int lim = min(base + CH, NN);
    int sum = 0;
    for (int i = base; i < lim; i++) sum += g_deg[i];
    partials[t] = sum;
    __syncthreads();
    for (int ofs = 1; ofs < 1024; ofs <<= 1) {
        int v = (t >= ofs) ? partials[t - ofs] : 0;
        __syncthreads();
        partials[t] += v;
        __syncthreads();
    }
    int run = partials[t] - sum;
    for (int i = base; i < lim; i++) {
        g_off[i] = run;
        g_cursor[i] = run;
        run += g_deg[i];
    }
    if (base <= NN && base + CH > NN) g_off[NN] = E;
}

__global__ void scatter_kernel(const int* __restrict__ src, const int* __restrict__ dst, int E) {
    int e = blockIdx.x * blockDim.x + threadIdx.x;
    if (e >= E) return;
    int d = dst[e];
    int pos = atomicAdd(&g_cursor[d], 1);
    g_esrc[pos] = src[e];
}

// ---------------- double-buffered fp32 SGEMM ----------------
template<int BM, int BN, int BK, int TM, int TN, bool RELU_IN>
__global__ __launch_bounds__((BM / TM) * (BN / TN))
void sgemm(const float* __restrict__ A, const float* __restrict__ B,
           float* __restrict__ C, int M, int Kd, int Nd) {
    constexpr int NTH = (BM / TM) * (BN / TN);
    constexpr int LA = (BM * BK / 4) / NTH;
    constexpr int LB = (BK * BN / 4) / NTH;
    __shared__ float As[2][BK][BM];
    __shared__ float Bs[2][BK][BN];
    const int tid = threadIdx.x;
    const int tx = tid % (BN / TN);
    const int ty = tid / (BN / TN);
    const int rowBase = blockIdx.x * BM;

    float4 pa[LA], pb[LB];
    float acc[TM][TN];
#pragma unroll
    for (int i = 0; i < TM; i++)
#pragma unroll
        for (int j = 0; j < TN; j++) acc[i][j] = 0.f;

    auto ldA = [&](int k0) {
#pragma unroll
        for (int l = 0; l < LA; l++) {
            int i = tid + l * NTH;
            int r = i / (BK / 4), c4 = (i % (BK / 4)) * 4;
            int grow = rowBase + r;
            float4 v = make_float4(0.f, 0.f, 0.f, 0.f);
            if (grow < M) v = *reinterpret_cast<const float4*>(A + (size_t)grow * Kd + k0 + c4);
            if (RELU_IN) {
                v.x = fmaxf(v.x, 0.f); v.y = fmaxf(v.y, 0.f);
                v.z = fmaxf(v.z, 0.f); v.w = fmaxf(v.w, 0.f);
            }
            pa[l] = v;
        }
    };
    auto ldB = [&](int k0) {
#pragma unroll
        for (int l = 0; l < LB; l++) {
            int i = tid + l * NTH;
            int r = i / (BN / 4), c4 = (i % (BN / 4)) * 4;
            pb[l] = *reinterpret_cast<const float4*>(B + (size_t)(k0 + r) * Nd + c4);
        }
    };
    auto stAB = [&](int buf) {
#pragma unroll
        for (int l = 0; l < LA; l++) {
            int i = tid + l * NTH;
            int r = i / (BK / 4), c4 = (i % (BK / 4)) * 4;
            As[buf][c4 + 0][r] = pa[l].x; As[buf][c4 + 1][r] = pa[l].y;
            As[buf][c4 + 2][r] = pa[l].z; As[buf][c4 + 3][r] = pa[l].w;
        }
#pragma unroll
        for (int l = 0; l < LB; l++) {
            int i = tid + l * NTH;
            int r = i / (BN / 4), c4 = (i % (BN / 4)) * 4;
            *reinterpret_cast<float4*>(&Bs[buf][r][c4]) = pb[l];
        }
    };

    ldA(0); ldB(0); stAB(0);
    __syncthreads();
    const int KT = Kd / BK;
    for (int kt = 0; kt < KT; kt++) {
        int cur = kt & 1;
        if (kt + 1 < KT) { ldA((kt + 1) * BK); ldB((kt + 1) * BK); }
#pragma unroll
        for (int kk = 0; kk < BK; kk++) {
            float a[TM], b[TN];
#pragma unroll
            for (int i = 0; i < TM; i += 4) {
                float4 av = *reinterpret_cast<const float4*>(&As[cur][kk][ty * TM + i]);
                a[i] = av.x; a[i + 1] = av.y; a[i + 2] = av.z; a[i + 3] = av.w;
            }
#pragma unroll
            for (int j = 0; j < TN; j += 4) {
                float4 bv = *reinterpret_cast<const float4*>(&Bs[cur][kk][tx * TN + j]);
                b[j] = bv.x; b[j + 1] = bv.y; b[j + 2] = bv.z; b[j + 3] = bv.w;
            }
#pragma unroll
            for (int i = 0; i < TM; i++)
#pragma unroll
                for (int j = 0; j < TN; j++)
                    acc[i][j] = fmaf(a[i], b[j], acc[i][j]);
        }
        if (kt + 1 < KT) { stAB(cur ^ 1); __syncthreads(); }
    }
#pragma unroll
    for (int i = 0; i < TM; i++) {
        int r = rowBase + ty * TM + i;
        if (r < M) {
#pragma unroll
            for (int j = 0; j < TN; j += 4) {
                float4 v = make_float4(acc[i][j], acc[i][j + 1], acc[i][j + 2], acc[i][j + 3]);
                *reinterpret_cast<float4*>(C + (size_t)r * Nd + tx * TN + j) = v;
            }
        }
    }
}

// ---------------- per-node el/er + fp16 mirror, layer1: warp per node ----------------
__global__ void elr1_kernel(const float* __restrict__ attn_l, const float* __restrict__ attn_r) {
    int t = blockIdx.x * blockDim.x + threadIdx.x;
    int node = t >> 5;
    if (node >= NN) return;
    int lane = t & 31;
    int h = lane >> 2, q = lane & 3;
    float4 f  = *reinterpret_cast<const float4*>(g_feat1 + (size_t)node * F_HID + lane * 4);
    // fp16 mirror (4 halves per lane)
    half2 m0 = __floats2half2_rn(f.x, f.y);
    half2 m1 = __floats2half2_rn(f.z, f.w);
    uint2 mu; mu.x = *reinterpret_cast<unsigned*>(&m0); mu.y = *reinterpret_cast<unsigned*>(&m1);
    *reinterpret_cast<uint2*>(g_feat1h + (size_t)node * F_HID + lane * 4) = mu;

    float4 al = *reinterpret_cast<const float4*>(attn_l + h * 16 + q * 4);
    float4 ar = *reinterpret_cast<const float4*>(attn_r + h * 16 + q * 4);
    float pl = f.x * al.x + f.y * al.y + f.z * al.z + f.w * al.w;
    float pr = f.x * ar.x + f.y * ar.y + f.z * ar.z + f.w * ar.w;
    pl += __shfl_xor_sync(0xffffffffu, pl, 1);
    pl += __shfl_xor_sync(0xffffffffu, pl, 2);
    pr += __shfl_xor_sync(0xffffffffu, pr, 1);
    pr += __shfl_xor_sync(0xffffffffu, pr, 2);
    if (q == 0) { g_el1[node * H1 + h] = pl; g_er1[node * H1 + h] = pr; }
}

// ---------------- per-node el/er + fp16 mirror, layer2: half-warp per node ----------------
__global__ void elr2_kernel(const float* __restrict__ attn_l, const float* __restrict__ attn_r) {
    int t = blockIdx.x * blockDim.x + threadIdx.x;
    int lane = t & 31;
    int half_id = lane >> 4;
    int sub  = lane & 15;
    int node = ((t >> 5) << 1) + half_id;
    float pl = 0.f, pr = 0.f;
    if (node < NN) {
        float4 f  = *reinterpret_cast<const float4*>(g_feat2 + (size_t)node * F_OUT + sub * 4);
        half2 m0 = __floats2half2_rn(f.x, f.y);
        half2 m1 = __floats2half2_rn(f.z, f.w);
        uint2 mu; mu.x = *reinterpret_cast<unsigned*>(&m0); mu.y = *reinterpret_cast<unsigned*>(&m1);
        *reinterpret_cast<uint2*>(g_feat2h + (size_t)node * F_OUT + sub * 4) = mu;

        float4 al = *reinterpret_cast<const float4*>(attn_l + sub * 4);
        float4 ar = *reinterpret_cast<const float4*>(attn_r + sub * 4);
        pl = f.x * al.x + f.y * al.y + f.z * al.z + f.w * al.w;
        pr = f.x * ar.x + f.y * ar.y + f.z * ar.z + f.w * ar.w;
    }
#pragma unroll
    for (int k = 1; k < 16; k <<= 1) {
        pl += __shfl_xor_sync(0xffffffffu, pl, k);
        pr += __shfl_xor_sync(0xffffffffu, pr, k);
    }
    if (sub == 0 && node < NN) { g_el2[node] = pl; g_er2[node] = pr; }
}

// ---------------- layer1 fused softmax+aggregate: warp per dst node (fp16 gather) -----------
__global__ void agg1_kernel(const float* __restrict__ bias1) {
    int t = blockIdx.x * blockDim.x + threadIdx.x;
    int w = t >> 5;
    if (w >= NN) return;
    int lane = t & 31;
    int h = lane >> 2;

    int beg = g_off[w], end = g_off[w + 1];
    float er_p = __ldg(g_er1 + (size_t)w * H1 + (lane & 7)); // p-duty role head

    float acc0 = 0.f, acc1 = 0.f, acc2 = 0.f, acc3 = 0.f, ssum = 0.f;

    for (int i0 = beg; i0 < end; i0 += 32) {
        int n = end - i0; if (n > 32) n = 32;
        int sreg = __ldg(g_esrc + i0 + min(lane, n - 1));
        for (int jb = 0; jb < n; jb += 4) {
            int je = jb + (lane >> 3); if (je > n - 1) je = n - 1;
            int sj = __shfl_sync(0xffffffffu, sreg, je);
            float pm = __expf(leaky(__ldg(g_el1 + (size_t)sj * H1 + (lane & 7)) + er_p));
#pragma unroll
            for (int j2 = 0; j2 < 4; j2++) {
                int j = jb + j2;
                int s = __shfl_sync(0xffffffffu, sreg, j < 32 ? j : 31);
                float p = __shfl_sync(0xffffffffu, pm, (j2 << 3) | h);
                if (j < n) {
                    uint2 u = *reinterpret_cast<const uint2*>(g_feat1h + (size_t)s * F_HID + lane * 4);
                    float2 f0 = __half22float2(*reinterpret_cast<half2*>(&u.x));
                    float2 f1 = __half22float2(*reinterpret_cast<half2*>(&u.y));
                    acc0 = fmaf(p, f0.x, acc0);
                    acc1 = fmaf(p, f0.y, acc1);
                    acc2 = fmaf(p, f1.x, acc2);
                    acc3 = fmaf(p, f1.y, acc3);
                    ssum += p;
                }
            }
        }
    }
    float inv = 1.f / fmaxf(ssum, 1e-9f);
    float4 b = *reinterpret_cast<const float4*>(bias1 + lane * 4);
    float4 o = make_float4(acc0 * inv + b.x, acc1 * inv + b.y,
                           acc2 * inv + b.z, acc3 * inv + b.w);
    *reinterpret_cast<float4*>(g_h1 + (size_t)w * F_HID + lane * 4) = o;
}

// ---------------- layer2 fused softmax+aggregate: warp per dst node (fp16 gather) -----------
__global__ void agg2_kernel(const float* __restrict__ bias2, float* __restrict__ out) {
    int t = blockIdx.x * blockDim.x + threadIdx.x;
    int w = t >> 5;
    if (w >= NN) return;
    int lane = t & 31;

    int beg = g_off[w], end = g_off[w + 1];
    float er = __ldg(g_er2 + w);

    float acc0 = 0.f, acc1 = 0.f, ssum = 0.f;

    for (int i0 = beg; i0 < end; i0 += 32) {
        int n = end - i0; if (n > 32) n = 32;
        int sreg = __ldg(g_esrc + i0 + min(lane, n - 1));
        float pl = __expf(leaky(__ldg(g_el2 + sreg) + er));
        for (int jb = 0; jb < n; jb += 4) {
#pragma unroll
            for (int j2 = 0; j2 < 4; j2++) {
                int j = jb + j2;
                int jc = j < 32 ? j : 31;
                int s   = __shfl_sync(0xffffffffu, sreg, jc);
                float p = __shfl_sync(0xffffffffu, pl, jc);
                if (j < n) {
                    unsigned u = *reinterpret_cast<const unsigned*>(g_feat2h + (size_t)s * F_OUT + lane * 2);
                    float2 f = __half22float2(*reinterpret_cast<half2*>(&u));
                    acc0 = fmaf(p, f.x, acc0);
                    acc1 = fmaf(p, f.y, acc1);
                    ssum += p;
                }
            }
        }
    }
    float inv = 1.f / fmaxf(ssum, 1e-9f);
    float2 b = *reinterpret_cast<const float2*>(bias2 + lane * 2);
    float2 o = make_float2(acc0 * inv + b.x, acc1 * inv + b.y);
    *reinterpret_cast<float2*>(out + (size_t)w * F_OUT + lane * 2) = o;
}

// ---------------- launch ----------------
extern "C" void kernel_launch(void* const* d_in, const int* in_sizes, int n_in,
                              void* d_out, int out_size) {
    const float* x   = (const float*)d_in[0];
    const int*   src = (const int*)  d_in[1];
    const int*   dst = (const int*)  d_in[2];
    const float* W1  = (const float*)d_in[3];
    const float* al1 = (const float*)d_in[4];
    const float* ar1 = (const float*)d_in[5];
    const float* b1  = (const float*)d_in[6];
    const float* W2  = (const float*)d_in[7];
    const float* al2 = (const float*)d_in[8];
    const float* ar2 = (const float*)d_in[9];
    const float* b2  = (const float*)d_in[10];
    float* out = (float*)d_out;
    const int E = in_sizes[1];
    const int M = NN;

    float *feat1, *h1, *feat2;
    cudaGetSymbolAddress((void**)&feat1, g_feat1);
    cudaGetSymbolAddress((void**)&h1,    g_h1);
    cudaGetSymbolAddress((void**)&feat2, g_feat2);

    static cudaStream_t s_side = nullptr;
    static cudaEvent_t  s_fork = nullptr, s_join = nullptr;
    if (!s_side) {
        cudaStreamCreateWithFlags(&s_side, cudaStreamNonBlocking);
        cudaEventCreateWithFlags(&s_fork, cudaEventDisableTiming);
        cudaEventCreateWithFlags(&s_join, cudaEventDisableTiming);
    }

    // fork: CSR build on side stream, concurrent with layer-1 GEMM + elr1
    cudaEventRecord(s_fork, 0);
    cudaStreamWaitEvent(s_side, s_fork, 0);
    init_kernel<<<(NN + 255) / 256, 256, 0, s_side>>>();
    hist_kernel<<<(E + 255) / 256, 256, 0, s_side>>>(dst, E);
    scan_kernel<<<1, 1024, 0, s_side>>>(E);
    scatter_kernel<<<(E + 255) / 256, 256, 0, s_side>>>(src, dst, E);
    cudaEventRecord(s_join, s_side);

    // main stream: layer-1 dense work
    sgemm<128, 128, 16, 8, 8, false><<<(M + 127) / 128, 256>>>(x, W1, feat1, M, F_IN, F_HID);
    elr1_kernel<<<(NN * 32 + 255) / 256, 256>>>(al1, ar1);

    cudaStreamWaitEvent(0, s_join, 0);
    agg1_kernel<<<(NN * 32 + 255) / 256, 256>>>(b1);

    // layer 2 (relu applied on A-load inside the GEMM)
    sgemm<128, 64, 16, 8, 4, true><<<(M + 127) / 128, 256>>>(h1, W2, feat2, M, F_HID, F_OUT);
    elr2_kernel<<<(((NN + 1) / 2) * 32 + 255) / 256, 256>>>(al2, ar2);
    agg2_kernel<<<(NN * 32 + 255) / 256, 256>>>(b2, out);
}

// round 6
// speedup vs baseline: 1.5655x; 1.1798x over previous
#include <cuda_runtime.h>
#include <cuda_fp16.h>
#include <cstdint>

#define NN     100000
#define F_IN   128
#define F_HID  128
#define F_OUT  64
#define H1     8
#define EDGES  1600000

// ---------------- scratch (static device globals; no allocs allowed) ----------------
__device__ float  g_feat1[NN * F_HID];   // layer1 projected features (fp32, for elr)
__device__ __half g_feat1h[NN * F_HID];  // fp16 mirror for gather
__device__ float  g_el1[NN * H1];
__device__ float  g_er1[NN * H1];
__device__ float  g_h1 [NN * F_HID];     // layer1 output (bias added, pre-relu)
__device__ float  g_feat2[NN * F_OUT];   // layer2 projected features
__device__ __half g_feat2h[NN * F_OUT];  // fp16 mirror for gather
__device__ float  g_el2[NN];
__device__ float  g_er2[NN];
// CSR by dst
__device__ int g_deg[NN];
__device__ int g_off[NN + 1];
__device__ int g_cursor[NN];
__device__ int g_esrc[EDGES];            // src node per edge, bucketed by dst

__device__ __forceinline__ float leaky(float v) { return v > 0.f ? v : 0.2f * v; }

// ---------------- init: zero degree counters ----------------
__global__ void init_kernel() {
    int i = blockIdx.x * blockDim.x + threadIdx.x;
    if (i < NN) g_deg[i] = 0;
}

// ---------------- CSR build ----------------
__global__ void hist_kernel(const int* __restrict__ dst, int E) {
    int e = blockIdx.x * blockDim.x + threadIdx.x;
    if (e < E) atomicAdd(&g_deg[dst[e]], 1);
}

__global__ void scan_kernel(int E) {
    __shared__ int partials[1024];
    const int CH = (NN + 1023) / 1024;   // 98
    int t = threadIdx.x;
    int base = t * CH;
    int lim = min(base + CH, NN);
    int sum = 0;
    for (int i = base; i < lim; i++) sum += g_deg[i];
    partials[t] = sum;
    __syncthreads();
    for (int ofs = 1; ofs < 1024; ofs <<= 1) {
        int v = (t >= ofs) ? partials[t - ofs] : 0;
        __syncthreads();
        partials[t] += v;
        __syncthreads();
    }
    int run = partials[t] - sum;
    for (int i = base; i < lim; i++) {
        g_off[i] = run;
        g_cursor[i] = run;
        run += g_deg[i];
    }
    if (base <= NN && base + CH > NN) g_off[NN] = E;
}

__global__ void scatter_kernel(const int* __restrict__ src, const int* __restrict__ dst, int E) {
    int e = blockIdx.x * blockDim.x + threadIdx.x;
    if (e >= E) return;
    int d = dst[e];
    int pos = atomicAdd(&g_cursor[d], 1);
    g_esrc[pos] = src[e];
}

// ---------------- tensor-core fp16 GEMM: C[M,BN] = A[M,Kd] @ B[Kd,BN] ----------------
__device__ __forceinline__ uint32_t smem_u32(const void* p) {
    return (uint32_t)__cvta_generic_to_shared(p);
}
__device__ __forceinline__ void ldm_x4(uint32_t& r0, uint32_t& r1, uint32_t& r2, uint32_t& r3,
                                       uint32_t addr) {
    asm volatile("ldmatrix.sync.aligned.m8n8.x4.shared.b16 {%0,%1,%2,%3}, [%4];"
                 : "=r"(r0), "=r"(r1), "=r"(r2), "=r"(r3) : "r"(addr));
}
__device__ __forceinline__ void ldm_x4_t(uint32_t& r0, uint32_t& r1, uint32_t& r2, uint32_t& r3,
                                         uint32_t addr) {
    asm volatile("ldmatrix.sync.aligned.m8n8.x4.trans.shared.b16 {%0,%1,%2,%3}, [%4];"
                 : "=r"(r0), "=r"(r1), "=r"(r2), "=r"(r3) : "r"(addr));
}
__device__ __forceinline__ void mma16816(float& d0, float& d1, float& d2, float& d3,
                                         uint32_t a0, uint32_t a1, uint32_t a2, uint32_t a3,
                                         uint32_t b0, uint32_t b1) {
    asm volatile("mma.sync.aligned.m16n8k16.row.col.f32.f16.f16.f32 "
                 "{%0,%1,%2,%3}, {%4,%5,%6,%7}, {%8,%9}, {%0,%1,%2,%3};"
                 : "+f"(d0), "+f"(d1), "+f"(d2), "+f"(d3)
                 : "r"(a0), "r"(a1), "r"(a2), "r"(a3), "r"(b0), "r"(b1));
}

template<int BN, bool RELU_IN>
__global__ __launch_bounds__(256)
void hgemm(const float* __restrict__ A, const float* __restrict__ B,
           float* __restrict__ C, int M, int Kd) {
    constexpr int BM = 128, BK = 32;
    constexpr int APAD = 8, BPAD = 8;
    constexpr int WN = BN / 2;       // warp n-extent (warps 4x2)
    constexpr int NT = WN / 8;       // B tiles per warp in n
    __shared__ __align__(16) __half As[2][BM][BK + APAD];
    __shared__ __align__(16) __half Bs[2][BK][BN + BPAD];

    const int tid = threadIdx.x;
    const int wid = tid >> 5, lane = tid & 31;
    const int wm = wid & 3, wn = wid >> 2;
    const int rowBase = blockIdx.x * BM;

    float acc[2][NT][4];
#pragma unroll
    for (int i = 0; i < 2; i++)
#pragma unroll
        for (int j = 0; j < NT; j++)
#pragma unroll
            for (int k = 0; k < 4; k++) acc[i][j][k] = 0.f;

    auto loadA = [&](int buf, int k0) {
#pragma unroll
        for (int it = 0; it < 2; it++) {
            int slot = tid + it * 256;       // 512 slots: 128 rows x 4 col-groups
            int r = slot >> 2;
            int c8 = (slot & 3) * 8;
            int grow = rowBase + r;
            float4 v0 = make_float4(0.f, 0.f, 0.f, 0.f), v1 = v0;
            if (grow < M) {
                const float* p = A + (size_t)grow * Kd + k0 + c8;
                v0 = *reinterpret_cast<const float4*>(p);
                v1 = *reinterpret_cast<const float4*>(p + 4);
            }
            if (RELU_IN) {
                v0.x = fmaxf(v0.x, 0.f); v0.y = fmaxf(v0.y, 0.f);
                v0.z = fmaxf(v0.z, 0.f); v0.w = fmaxf(v0.w, 0.f);
                v1.x = fmaxf(v1.x, 0.f); v1.y = fmaxf(v1.y, 0.f);
                v1.z = fmaxf(v1.z, 0.f); v1.w = fmaxf(v1.w, 0.f);
            }
            half2 h0 = __floats2half2_rn(v0.x, v0.y);
            half2 h1 = __floats2half2_rn(v0.z, v0.w);
            half2 h2 = __floats2half2_rn(v1.x, v1.y);
            half2 h3 = __floats2half2_rn(v1.z, v1.w);
            uint4 u;
            u.x = *reinterpret_cast<unsigned*>(&h0);
            u.y = *reinterpret_cast<unsigned*>(&h1);
            u.z = *reinterpret_cast<unsigned*>(&h2);
            u.w = *reinterpret_cast<unsigned*>(&h3);
            *reinterpret_cast<uint4*>(&As[buf][r][c8]) = u;
        }
    };
    auto loadB = [&](int buf, int k0) {
        constexpr int CG = BN / 8;           // col groups
        constexpr int SLOTS = BK * CG;       // 32*CG
        constexpr int ITERS = SLOTS / 256;   // BN=128 -> 2, BN=64 -> 1
#pragma unroll
        for (int it = 0; it < (ITERS > 0 ? ITERS : 1); it++) {
            int slot = tid + it * 256;
            if (SLOTS < 256 && slot >= SLOTS) break;
            int r = slot / CG;
            int c8 = (slot % CG) * 8;
            const float* p = B + (size_t)(k0 + r) * BN + c8;
            float4 v0 = *reinterpret_cast<const float4*>(p);
            float4 v1 = *reinterpret_cast<const float4*>(p + 4);
            half2 h0 = __floats2half2_rn(v0.x, v0.y);
            half2 h1 = __floats2half2_rn(v0.z, v0.w);
            half2 h2 = __floats2half2_rn(v1.x, v1.y);
            half2 h3 = __floats2half2_rn(v1.z, v1.w);
            uint4 u;
            u.x = *reinterpret_cast<unsigned*>(&h0);
            u.y = *reinterpret_cast<unsigned*>(&h1);
            u.z = *reinterpret_cast<unsigned*>(&h2);
            u.w = *reinterpret_cast<unsigned*>(&h3);
            *reinterpret_cast<uint4*>(&Bs[buf][r][c8]) = u;
        }
    };

    loadA(0, 0); loadB(0, 0);
    __syncthreads();
    const int KT = Kd / BK;
    for (int kt = 0; kt < KT; kt++) {
        int buf = kt & 1;
        if (kt + 1 < KT) { loadA(buf ^ 1, (kt + 1) * BK); loadB(buf ^ 1, (kt + 1) * BK); }
#pragma unroll
        for (int kc = 0; kc < 2; kc++) {
            int k16 = kc * 16;
            uint32_t af[2][4];
#pragma unroll
            for (int mt = 0; mt < 2; mt++) {
                uint32_t addr = smem_u32(&As[buf][wm * 32 + mt * 16 + (lane & 15)][k16 + (lane >> 4) * 8]);
                ldm_x4(af[mt][0], af[mt][1], af[mt][2], af[mt][3], addr);
            }
            uint32_t bf[NT][2];
#pragma unroll
            for (int nt2 = 0; nt2 < NT / 2; nt2++) {
                uint32_t addr = smem_u32(&Bs[buf][k16 + (lane & 15)][wn * WN + nt2 * 16 + (lane >> 4) * 8]);
                uint32_t r0, r1, r2, r3;
                ldm_x4_t(r0, r1, r2, r3, addr);
                bf[nt2 * 2][0] = r0; bf[nt2 * 2][1] = r1;
                bf[nt2 * 2 + 1][0] = r2; bf[nt2 * 2 + 1][1] = r3;
            }
#pragma unroll
            for (int mt = 0; mt < 2; mt++)
#pragma unroll
                for (int nt = 0; nt < NT; nt++)
                    mma16816(acc[mt][nt][0], acc[mt][nt][1], acc[mt][nt][2], acc[mt][nt][3],
                             af[mt][0], af[mt][1], af[mt][2], af[mt][3],
                             bf[nt][0], bf[nt][1]);
        }
        __syncthreads();
    }

    // epilogue
    const int gid = lane >> 2, qid = lane & 3;
#pragma unroll
    for (int mt = 0; mt < 2; mt++) {
        int r0 = rowBase + wm * 32 + mt * 16 + gid;
#pragma unroll
        for (int nt = 0; nt < NT; nt++) {
            int c = wn * WN + nt * 8 + qid * 2;
            if (r0 < M)
                *reinterpret_cast<float2*>(C + (size_t)r0 * BN + c) =
                    make_float2(acc[mt][nt][0], acc[mt][nt][1]);
            if (r0 + 8 < M)
                *reinterpret_cast<float2*>(C + (size_t)(r0 + 8) * BN + c) =
                    make_float2(acc[mt][nt][2], acc[mt][nt][3]);
        }
    }
}

// ---------------- per-node el/er + fp16 mirror, layer1: warp per node ----------------
__global__ void elr1_kernel(const float* __restrict__ attn_l, const float* __restrict__ attn_r) {
    int t = blockIdx.x * blockDim.x + threadIdx.x;
    int node = t >> 5;
    if (node >= NN) return;
    int lane = t & 31;
    int h = lane >> 2, q = lane & 3;
    float4 f  = *reinterpret_cast<const float4*>(g_feat1 + (size_t)node * F_HID + lane * 4);
    half2 m0 = __floats2half2_rn(f.x, f.y);
    half2 m1 = __floats2half2_rn(f.z, f.w);
    uint2 mu; mu.x = *reinterpret_cast<unsigned*>(&m0); mu.y = *reinterpret_cast<unsigned*>(&m1);
    *reinterpret_cast<uint2*>(g_feat1h + (size_t)node * F_HID + lane * 4) = mu;

    float4 al = *reinterpret_cast<const float4*>(attn_l + h * 16 + q * 4);
    float4 ar = *reinterpret_cast<const float4*>(attn_r + h * 16 + q * 4);
    float pl = f.x * al.x + f.y * al.y + f.z * al.z + f.w * al.w;
    float pr = f.x * ar.x + f.y * ar.y + f.z * ar.z + f.w * ar.w;
    pl += __shfl_xor_sync(0xffffffffu, pl, 1);
    pl += __shfl_xor_sync(0xffffffffu, pl, 2);
    pr += __shfl_xor_sync(0xffffffffu, pr, 1);
    pr += __shfl_xor_sync(0xffffffffu, pr, 2);
    if (q == 0) { g_el1[node * H1 + h] = pl; g_er1[node * H1 + h] = pr; }
}

// ---------------- per-node el/er + fp16 mirror, layer2: half-warp per node ----------------
__global__ void elr2_kernel(const float* __restrict__ attn_l, const float* __restrict__ attn_r) {
    int t = blockIdx.x * blockDim.x + threadIdx.x;
    int lane = t & 31;
    int half_id = lane >> 4;
    int sub  = lane & 15;
    int node = ((t >> 5) << 1) + half_id;
    float pl = 0.f, pr = 0.f;
    if (node < NN) {
        float4 f  = *reinterpret_cast<const float4*>(g_feat2 + (size_t)node * F_OUT + sub * 4);
        half2 m0 = __floats2half2_rn(f.x, f.y);
        half2 m1 = __floats2half2_rn(f.z, f.w);
        uint2 mu; mu.x = *reinterpret_cast<unsigned*>(&m0); mu.y = *reinterpret_cast<unsigned*>(&m1);
        *reinterpret_cast<uint2*>(g_feat2h + (size_t)node * F_OUT + sub * 4) = mu;

        float4 al = *reinterpret_cast<const float4*>(attn_l + sub * 4);
        float4 ar = *reinterpret_cast<const float4*>(attn_r + sub * 4);
        pl = f.x * al.x + f.y * al.y + f.z * al.z + f.w * al.w;
        pr = f.x * ar.x + f.y * ar.y + f.z * ar.z + f.w * ar.w;
    }
#pragma unroll
    for (int k = 1; k < 16; k <<= 1) {
        pl += __shfl_xor_sync(0xffffffffu, pl, k);
        pr += __shfl_xor_sync(0xffffffffu, pr, k);
    }
    if (sub == 0 && node < NN) { g_el2[node] = pl; g_er2[node] = pr; }
}

// ---------------- layer1 fused softmax+aggregate: warp per dst node ----------------
// per-lane direct el gather (8 heads of a node = one 32B sector, 4-lane broadcast)
__global__ void agg1_kernel(const float* __restrict__ bias1) {
    int t = blockIdx.x * blockDim.x + threadIdx.x;
    int w = t >> 5;
    if (w >= NN) return;
    int lane = t & 31;
    int h = lane >> 2;

    int beg = g_off[w], end = g_off[w + 1];
    float er_h = __ldg(g_er1 + (size_t)w * H1 + h);

    float acc0 = 0.f, acc1 = 0.f, acc2 = 0.f, acc3 = 0.f, ssum = 0.f;

    for (int i0 = beg; i0 < end; i0 += 32) {
        int n = end - i0; if (n > 32) n = 32;
        int sreg = __ldg(g_esrc + i0 + min(lane, n - 1));
        for (int jb = 0; jb < n; jb += 4) {
            int s0 = __shfl_sync(0xffffffffu, sreg, jb);
            int s1 = __shfl_sync(0xffffffffu, sreg, jb + 1);
            int s2 = __shfl_sync(0xffffffffu, sreg, jb + 2);
            int s3 = __shfl_sync(0xffffffffu, sreg, jb + 3);
            // hoisted independent loads (8 in flight)
            float el0 = __ldg(g_el1 + (size_t)s0 * H1 + h);
            float el1 = __ldg(g_el1 + (size_t)s1 * H1 + h);
            float el2 = __ldg(g_el1 + (size_t)s2 * H1 + h);
            float el3 = __ldg(g_el1 + (size_t)s3 * H1 + h);
            uint2 u0 = *reinterpret_cast<const uint2*>(g_feat1h + (size_t)s0 * F_HID + lane * 4);
            uint2 u1 = *reinterpret_cast<const uint2*>(g_feat1h + (size_t)s1 * F_HID + lane * 4);
            uint2 u2 = *reinterpret_cast<const uint2*>(g_feat1h + (size_t)s2 * F_HID + lane * 4);
            uint2 u3 = *reinterpret_cast<const uint2*>(g_feat1h + (size_t)s3 * F_HID + lane * 4);
            float p0 = __expf(leaky(el0 + er_h)); if (jb + 0 >= n) p0 = 0.f;
            float p1 = __expf(leaky(el1 + er_h)); if (jb + 1 >= n) p1 = 0.f;
            float p2 = __expf(leaky(el2 + er_h)); if (jb + 2 >= n) p2 = 0.f;
            float p3 = __expf(leaky(el3 + er_h)); if (jb + 3 >= n) p3 = 0.f;
            {
                float2 a = __half22float2(*reinterpret_cast<half2*>(&u0.x));
                float2 b = __half22float2(*reinterpret_cast<half2*>(&u0.y));
                acc0 = fmaf(p0, a.x, acc0); acc1 = fmaf(p0, a.y, acc1);
                acc2 = fmaf(p0, b.x, acc2); acc3 = fmaf(p0, b.y, acc3);
            }
            {
                float2 a = __half22float2(*reinterpret_cast<half2*>(&u1.x));
                float2 b = __half22float2(*reinterpret_cast<half2*>(&u1.y));
                acc0 = fmaf(p1, a.x, acc0); acc1 = fmaf(p1, a.y, acc1);
                acc2 = fmaf(p1, b.x, acc2); acc3 = fmaf(p1, b.y, acc3);
            }
            {
                float2 a = __half22float2(*reinterpret_cast<half2*>(&u2.x));
                float2 b = __half22float2(*reinterpret_cast<half2*>(&u2.y));
                acc0 = fmaf(p2, a.x, acc0); acc1 = fmaf(p2, a.y, acc1);
                acc2 = fmaf(p2, b.x, acc2); acc3 = fmaf(p2, b.y, acc3);
            }
            {
                float2 a = __half22float2(*reinterpret_cast<half2*>(&u3.x));
                float2 b = __half22float2(*reinterpret_cast<half2*>(&u3.y));
                acc0 = fmaf(p3, a.x, acc0); acc1 = fmaf(p3, a.y, acc1);
                acc2 = fmaf(p3, b.x, acc2); acc3 = fmaf(p3, b.y, acc3);
            }
            ssum += (p0 + p1) + (p2 + p3);
        }
    }
    float inv = 1.f / fmaxf(ssum, 1e-9f);
    float4 b = *reinterpret_cast<const float4*>(bias1 + lane * 4);
    float4 o = make_float4(acc0 * inv + b.x, acc1 * inv + b.y,
                           acc2 * inv + b.z, acc3 * inv + b.w);
    *reinterpret_cast<float4*>(g_h1 + (size_t)w * F_HID + lane * 4) = o;
}

// ---------------- layer2 fused softmax+aggregate: warp per dst node (64 floats) -------------
__global__ void agg2_kernel(const float* __restrict__ bias2, float* __restrict__ out) {
    int t = blockIdx.x * blockDim.x + threadIdx.x;
    int w = t >> 5;
    if (w >= NN) return;
    int lane = t & 31;

    int beg = g_off[w], end = g_off[w + 1];
    float er = __ldg(g_er2 + w);

    float acc0 = 0.f, acc1 = 0.f, ssum = 0.f;

    for (int i0 = beg; i0 < end; i0 += 32) {
        int n = end - i0; if (n > 32) n = 32;
        int sreg = __ldg(g_esrc + i0 + min(lane, n - 1));
        float pl = __expf(leaky(__ldg(g_el2 + sreg) + er));
        for (int jb = 0; jb < n; jb += 4) {
            int s0 = __shfl_sync(0xffffffffu, sreg, jb);
            int s1 = __shfl_sync(0xffffffffu, sreg, jb + 1);
            int s2 = __shfl_sync(0xffffffffu, sreg, jb + 2);
            int s3 = __shfl_sync(0xffffffffu, sreg, jb + 3);
            float p0 = __shfl_sync(0xffffffffu, pl, jb);
            float p1 = __shfl_sync(0xffffffffu, pl, jb + 1);
            float p2 = __shfl_sync(0xffffffffu, pl, jb + 2);
            float p3 = __shfl_sync(0xffffffffu, pl, jb + 3);
            if (jb + 0 >= n) p0 = 0.f;
            if (jb + 1 >= n) p1 = 0.f;
            if (jb + 2 >= n) p2 = 0.f;
            if (jb + 3 >= n) p3 = 0.f;
            unsigned u0 = *reinterpret_cast<const unsigned*>(g_feat2h + (size_t)s0 * F_OUT + lane * 2);
            unsigned u1 = *reinterpret_cast<const unsigned*>(g_feat2h + (size_t)s1 * F_OUT + lane * 2);
            unsigned u2 = *reinterpret_cast<const unsigned*>(g_feat2h + (size_t)s2 * F_OUT + lane * 2);
            unsigned u3 = *reinterpret_cast<const unsigned*>(g_feat2h + (size_t)s3 * F_OUT + lane * 2);
            float2 f0 = __half22float2(*reinterpret_cast<half2*>(&u0));
            float2 f1 = __half22float2(*reinterpret_cast<half2*>(&u1));
            float2 f2 = __half22float2(*reinterpret_cast<half2*>(&u2));
            float2 f3 = __half22float2(*reinterpret_cast<half2*>(&u3));
            acc0 = fmaf(p0, f0.x, acc0); acc1 = fmaf(p0, f0.y, acc1);
            acc0 = fmaf(p1, f1.x, acc0); acc1 = fmaf(p1, f1.y, acc1);
            acc0 = fmaf(p2, f2.x, acc0); acc1 = fmaf(p2, f2.y, acc1);
            acc0 = fmaf(p3, f3.x, acc0); acc1 = fmaf(p3, f3.y, acc1);
            ssum += (p0 + p1) + (p2 + p3);
        }
    }
    float inv = 1.f / fmaxf(ssum, 1e-9f);
    float2 b = *reinterpret_cast<const float2*>(bias2 + lane * 2);
    float2 o = make_float2(acc0 * inv + b.x, acc1 * inv + b.y);
    *reinterpret_cast<float2*>(out + (size_t)w * F_OUT + lane * 2) = o;
}

// ---------------- launch ----------------
extern "C" void kernel_launch(void* const* d_in, const int* in_sizes, int n_in,
                              void* d_out, int out_size) {
    const float* x   = (const float*)d_in[0];
    const int*   src = (const int*)  d_in[1];
    const int*   dst = (const int*)  d_in[2];
    const float* W1  = (const float*)d_in[3];
    const float* al1 = (const float*)d_in[4];
    const float* ar1 = (const float*)d_in[5];
    const float* b1  = (const float*)d_in[6];
    const float* W2  = (const float*)d_in[7];
    const float* al2 = (const float*)d_in[8];
    const float* ar2 = (const float*)d_in[9];
    const float* b2  = (const float*)d_in[10];
    float* out = (float*)d_out;
    const int E = in_sizes[1];
    const int M = NN;

    float *feat1, *h1, *feat2;
    cudaGetSymbolAddress((void**)&feat1, g_feat1);
    cudaGetSymbolAddress((void**)&h1,    g_h1);
    cudaGetSymbolAddress((void**)&feat2, g_feat2);

    static cudaStream_t s_side = nullptr;
    static cudaEvent_t  s_fork = nullptr, s_join = nullptr;
    if (!s_side) {
        cudaStreamCreateWithFlags(&s_side, cudaStreamNonBlocking);
        cudaEventCreateWithFlags(&s_fork, cudaEventDisableTiming);
        cudaEventCreateWithFlags(&s_join, cudaEventDisableTiming);
    }

    // fork: CSR build on side stream, concurrent with layer-1 GEMM + elr1
    cudaEventRecord(s_fork, 0);
    cudaStreamWaitEvent(s_side, s_fork, 0);
    init_kernel<<<(NN + 255) / 256, 256, 0, s_side>>>();
    hist_kernel<<<(E + 255) / 256, 256, 0, s_side>>>(dst, E);
    scan_kernel<<<1, 1024, 0, s_side>>>(E);
    scatter_kernel<<<(E + 255) / 256, 256, 0, s_side>>>(src, dst, E);
    cudaEventRecord(s_join, s_side);

    // main stream: layer-1 dense work (tensor-core GEMM)
    hgemm<F_HID, false><<<(M + 127) / 128, 256>>>(x, W1, feat1, M, F_IN);
    elr1_kernel<<<(NN * 32 + 255) / 256, 256>>>(al1, ar1);

    cudaStreamWaitEvent(0, s_join, 0);
    agg1_kernel<<<(NN * 32 + 255) / 256, 256>>>(b1);

    // layer 2 (relu applied on A-load inside the GEMM)
    hgemm<F_OUT, true><<<(M + 127) / 128, 256>>>(h1, W2, feat2, M, F_HID);
    elr2_kernel<<<(((NN + 1) / 2) * 32 + 255) / 256, 256>>>(al2, ar2);
    agg2_kernel<<<(NN * 32 + 255) / 256, 256>>>(b2, out);
}

// round 7
// speedup vs baseline: 1.6276x; 1.0396x over previous
#include <cuda_runtime.h>
#include <cuda_fp16.h>
#include <cstdint>

#define NN     100000
#define F_IN   128
#define F_HID  128
#define F_OUT  64
#define H1     8
#define EDGES  1600000

// ---------------- scratch (static device globals; no allocs allowed) ----------------
__device__ __half g_feat1h[NN * F_HID];  // layer1 features, fp16 (gather + mirror)
__device__ float  g_el1[NN * H1];
__device__ float  g_er1[NN * H1];
__device__ __half g_h1h[NN * F_HID];     // layer1 output (bias added, pre-relu), fp16
__device__ __half g_feat2h[NN * F_OUT];  // layer2 features, fp16
__device__ float  g_el2[NN];
__device__ float  g_er2[NN];
// CSR by dst
__device__ int g_deg[NN];
__device__ int g_off[NN + 1];
__device__ int g_cursor[NN];
__device__ int g_esrc[EDGES];

__device__ __forceinline__ float leaky(float v) { return v > 0.f ? v : 0.2f * v; }

// ---------------- init: zero degree counters ----------------
__global__ void init_kernel() {
    int i = blockIdx.x * blockDim.x + threadIdx.x;
    if (i < NN) g_deg[i] = 0;
}

// ---------------- CSR build (int4 vectorized) ----------------
__global__ void hist_kernel(const int* __restrict__ dst, int E) {
    int i = (blockIdx.x * blockDim.x + threadIdx.x) * 4;
    if (i + 4 <= E) {
        int4 d = *reinterpret_cast<const int4*>(dst + i);
        atomicAdd(&g_deg[d.x], 1);
        atomicAdd(&g_deg[d.y], 1);
        atomicAdd(&g_deg[d.z], 1);
        atomicAdd(&g_deg[d.w], 1);
    } else {
        for (; i < E; i++) atomicAdd(&g_deg[dst[i]], 1);
    }
}

__global__ void scan_kernel(int E) {
    __shared__ int partials[1024];
    const int CH = (NN + 1023) / 1024;
    int t = threadIdx.x;
    int base = t * CH;
    int lim = min(base + CH, NN);
    int sum = 0;
    for (int i = base; i < lim; i++) sum += g_deg[i];
    partials[t] = sum;
    __syncthreads();
    for (int ofs = 1; ofs < 1024; ofs <<= 1) {
        int v = (t >= ofs) ? partials[t - ofs] : 0;
        __syncthreads();
        partials[t] += v;
        __syncthreads();
    }
    int run = partials[t] - sum;
    for (int i = base; i < lim; i++) {
        g_off[i] = run;
        g_cursor[i] = run;
        run += g_deg[i];
    }
    if (base <= NN && base + CH > NN) g_off[NN] = E;
}

__global__ void scatter_kernel(const int* __restrict__ src, const int* __restrict__ dst, int E) {
    int i = (blockIdx.x * blockDim.x + threadIdx.x) * 4;
    if (i + 4 <= E) {
        int4 s = *reinterpret_cast<const int4*>(src + i);
        int4 d = *reinterpret_cast<const int4*>(dst + i);
        g_esrc[atomicAdd(&g_cursor[d.x], 1)] = s.x;
        g_esrc[atomicAdd(&g_cursor[d.y], 1)] = s.y;
        g_esrc[atomicAdd(&g_cursor[d.z], 1)] = s.z;
        g_esrc[atomicAdd(&g_cursor[d.w], 1)] = s.w;
    } else {
        for (; i < E; i++) g_esrc[atomicAdd(&g_cursor[dst[i]], 1)] = src[i];
    }
}

// ---------------- tensor-core fp16 GEMM + fused elr epilogue ----------------
__device__ __forceinline__ uint32_t smem_u32(const void* p) {
    return (uint32_t)__cvta_generic_to_shared(p);
}
__device__ __forceinline__ void ldm_x4(uint32_t& r0, uint32_t& r1, uint32_t& r2, uint32_t& r3,
                                       uint32_t addr) {
    asm volatile("ldmatrix.sync.aligned.m8n8.x4.shared.b16 {%0,%1,%2,%3}, [%4];"
                 : "=r"(r0), "=r"(r1), "=r"(r2), "=r"(r3) : "r"(addr));
}
__device__ __forceinline__ void ldm_x4_t(uint32_t& r0, uint32_t& r1, uint32_t& r2, uint32_t& r3,
                                         uint32_t addr) {
    asm volatile("ldmatrix.sync.aligned.m8n8.x4.trans.shared.b16 {%0,%1,%2,%3}, [%4];"
                 : "=r"(r0), "=r"(r1), "=r"(r2), "=r"(r3) : "r"(addr));
}
__device__ __forceinline__ void mma16816(float& d0, float& d1, float& d2, float& d3,
                                         uint32_t a0, uint32_t a1, uint32_t a2, uint32_t a3,
                                         uint32_t b0, uint32_t b1) {
    asm volatile("mma.sync.aligned.m16n8k16.row.col.f32.f16.f16.f32 "
                 "{%0,%1,%2,%3}, {%4,%5,%6,%7}, {%8,%9}, {%0,%1,%2,%3};"
                 : "+f"(d0), "+f"(d1), "+f"(d2), "+f"(d3)
                 : "r"(a0), "r"(a1), "r"(a2), "r"(a3), "r"(b0), "r"(b1));
}

// BN=128 (layer1): 8 heads of 16; head span inside warp -> in-warp elr reduction.
// BN=64  (layer2): 1 head of 64; cross-warp (wn) elr reduction via smem.
// Outputs: Ch fp16 mirror, gel/ger per-node scores. No fp32 C.
template<int BN, bool RELU_IN, typename AT>
__global__ __launch_bounds__(256)
void hgemm_fused(const AT* __restrict__ A, const float* __restrict__ B,
                 __half* __restrict__ Ch, float* __restrict__ gel, float* __restrict__ ger,
                 const float* __restrict__ attn_l, const float* __restrict__ attn_r,
                 int M, int Kd) {
    constexpr int BM = 128, BK = 32;
    constexpr int APAD = 8, BPAD = 8;
    constexpr int WN = BN / 2;
    constexpr int NT = WN / 8;
    __shared__ __align__(16) __half As[2][BM][BK + APAD];
    __shared__ __align__(16) __half Bs[2][BK][BN + BPAD];

    const int tid = threadIdx.x;
    const int wid = tid >> 5, lane = tid & 31;
    const int wm = wid & 3, wn = wid >> 2;
    const int rowBase = blockIdx.x * BM;

    float acc[2][NT][4];
#pragma unroll
    for (int i = 0; i < 2; i++)
#pragma unroll
        for (int j = 0; j < NT; j++)
#pragma unroll
            for (int k = 0; k < 4; k++) acc[i][j][k] = 0.f;

    auto loadA = [&](int buf, int k0) {
#pragma unroll
        for (int it = 0; it < 2; it++) {
            int slot = tid + it * 256;
            int r = slot >> 2;
            int c8 = (slot & 3) * 8;
            int grow = rowBase + r;
            if constexpr (sizeof(AT) == 2) {   // fp16 input (8 halves = 16B)
                uint4 u = make_uint4(0, 0, 0, 0);
                if (grow < M)
                    u = *reinterpret_cast<const uint4*>(A + (size_t)grow * Kd + k0 + c8);
                if (RELU_IN) {
                    half2 z = __float2half2_rn(0.f);
                    half2* hp = reinterpret_cast<half2*>(&u);
                    hp[0] = __hmax2(hp[0], z); hp[1] = __hmax2(hp[1], z);
                    hp[2] = __hmax2(hp[2], z); hp[3] = __hmax2(hp[3], z);
                }
                *reinterpret_cast<uint4*>(&As[buf][r][c8]) = u;
            } else {                            // fp32 input
                float4 v0 = make_float4(0.f, 0.f, 0.f, 0.f), v1 = v0;
                if (grow < M) {
                    const float* p = reinterpret_cast<const float*>(A) + (size_t)grow * Kd + k0 + c8;
                    v0 = *reinterpret_cast<const float4*>(p);
                    v1 = *reinterpret_cast<const float4*>(p + 4);
                }
                if (RELU_IN) {
                    v0.x = fmaxf(v0.x, 0.f); v0.y = fmaxf(v0.y, 0.f);
                    v0.z = fmaxf(v0.z, 0.f); v0.w = fmaxf(v0.w, 0.f);
                    v1.x = fmaxf(v1.x, 0.f); v1.y = fmaxf(v1.y, 0.f);
                    v1.z = fmaxf(v1.z, 0.f); v1.w = fmaxf(v1.w, 0.f);
                }
                half2 h0 = __floats2half2_rn(v0.x, v0.y);
                half2 h1 = __floats2half2_rn(v0.z, v0.w);
                half2 h2 = __floats2half2_rn(v1.x, v1.y);
                half2 h3 = __floats2half2_rn(v1.z, v1.w);
                uint4 u;
                u.x = *reinterpret_cast<unsigned*>(&h0);
                u.y = *reinterpret_cast<unsigned*>(&h1);
                u.z = *reinterpret_cast<unsigned*>(&h2);
                u.w = *reinterpret_cast<unsigned*>(&h3);
                *reinterpret_cast<uint4*>(&As[buf][r][c8]) = u;
            }
        }
    };
    auto loadB = [&](int buf, int k0) {
        constexpr int CG = BN / 8;
        constexpr int SLOTS = BK * CG;
        constexpr int ITERS = (SLOTS + 255) / 256;
#pragma unroll
        for (int it = 0; it < ITERS; it++) {
            int slot = tid + it * 256;
            if (SLOTS < 256 && slot >= SLOTS) break;
            int r = slot / CG;
            int c8 = (slot % CG) * 8;
            const float* p = B + (size_t)(k0 + r) * BN + c8;
            float4 v0 = *reinterpret_cast<const float4*>(p);
            float4 v1 = *reinterpret_cast<const float4*>(p + 4);
            half2 h0 = __floats2half2_rn(v0.x, v0.y);
            half2 h1 = __floats2half2_rn(v0.z, v0.w);
            half2 h2 = __floats2half2_rn(v1.x, v1.y);
            half2 h3 = __floats2half2_rn(v1.z, v1.w);
            uint4 u;
            u.x = *reinterpret_cast<unsigned*>(&h0);
            u.y = *reinterpret_cast<unsigned*>(&h1);
            u.z = *reinterpret_cast<unsigned*>(&h2);
            u.w = *reinterpret_cast<unsigned*>(&h3);
            *reinterpret_cast<uint4*>(&Bs[buf][r][c8]) = u;
        }
    };

    loadA(0, 0); loadB(0, 0);
    __syncthreads();
    const int KT = Kd / BK;
    for (int kt = 0; kt < KT; kt++) {
        int buf = kt & 1;
        if (kt + 1 < KT) { loadA(buf ^ 1, (kt + 1) * BK); loadB(buf ^ 1, (kt + 1) * BK); }
#pragma unroll
        for (int kc = 0; kc < 2; kc++) {
            int k16 = kc * 16;
            uint32_t af[2][4];
#pragma unroll
            for (int mt = 0; mt < 2; mt++) {
                uint32_t addr = smem_u32(&As[buf][wm * 32 + mt * 16 + (lane & 15)][k16 + (lane >> 4) * 8]);
                ldm_x4(af[mt][0], af[mt][1], af[mt][2], af[mt][3], addr);
            }
            uint32_t bf[NT][2];
#pragma unroll
            for (int nt2 = 0; nt2 < NT / 2; nt2++) {
                uint32_t addr = smem_u32(&Bs[buf][k16 + (lane & 15)][wn * WN + nt2 * 16 + (lane >> 4) * 8]);
                uint32_t r0, r1, r2, r3;
                ldm_x4_t(r0, r1, r2, r3, addr);
                bf[nt2 * 2][0] = r0; bf[nt2 * 2][1] = r1;
                bf[nt2 * 2 + 1][0] = r2; bf[nt2 * 2 + 1][1] = r3;
            }
#pragma unroll
            for (int mt = 0; mt < 2; mt++)
#pragma unroll
                for (int nt = 0; nt < NT; nt++)
                    mma16816(acc[mt][nt][0], acc[mt][nt][1], acc[mt][nt][2], acc[mt][nt][3],
                             af[mt][0], af[mt][1], af[mt][2], af[mt][3],
                             bf[nt][0], bf[nt][1]);
        }
        __syncthreads();
    }

    const int gid = lane >> 2, qid = lane & 3;

    // ---- fp16 mirror ----
#pragma unroll
    for (int mt = 0; mt < 2; mt++) {
        int r0 = rowBase + wm * 32 + mt * 16 + gid;
#pragma unroll
        for (int nt = 0; nt < NT; nt++) {
            int c = wn * WN + nt * 8 + qid * 2;
            if (r0 < M) {
                half2 hv = __floats2half2_rn(acc[mt][nt][0], acc[mt][nt][1]);
                *reinterpret_cast<unsigned*>(Ch + (size_t)r0 * BN + c) =
                    *reinterpret_cast<unsigned*>(&hv);
            }
            if (r0 + 8 < M) {
                half2 hv = __floats2half2_rn(acc[mt][nt][2], acc[mt][nt][3]);
                *reinterpret_cast<unsigned*>(Ch + (size_t)(r0 + 8) * BN + c) =
                    *reinterpret_cast<unsigned*>(&hv);
            }
        }
    }

    // ---- fused elr ----
    if constexpr (BN == 128) {
        // attn weights touched by this thread: 16 (el) + 16 (er)
        float wl[16], wr[16];
#pragma unroll
        for (int nt = 0; nt < 8; nt++) {
            int c = wn * 64 + nt * 8 + qid * 2;
            wl[nt * 2 + 0] = __ldg(attn_l + c);
            wl[nt * 2 + 1] = __ldg(attn_l + c + 1);
            wr[nt * 2 + 0] = __ldg(attn_r + c);
            wr[nt * 2 + 1] = __ldg(attn_r + c + 1);
        }
#pragma unroll
        for (int mt = 0; mt < 2; mt++)
#pragma unroll
            for (int hf = 0; hf < 2; hf++) {
                int r = rowBase + wm * 32 + mt * 16 + hf * 8 + gid;
                float sel[4], ser[4];
#pragma unroll
                for (int hl = 0; hl < 4; hl++) {
                    int n0 = hl * 2, n1 = hl * 2 + 1;
                    sel[hl] = acc[mt][n0][hf * 2] * wl[n0 * 2] + acc[mt][n0][hf * 2 + 1] * wl[n0 * 2 + 1]
                            + acc[mt][n1][hf * 2] * wl[n1 * 2] + acc[mt][n1][hf * 2 + 1] * wl[n1 * 2 + 1];
                    ser[hl] = acc[mt][n0][hf * 2] * wr[n0 * 2] + acc[mt][n0][hf * 2 + 1] * wr[n0 * 2 + 1]
                            + acc[mt][n1][hf * 2] * wr[n1 * 2] + acc[mt][n1][hf * 2 + 1] * wr[n1 * 2 + 1];
                }
#pragma unroll
                for (int hl = 0; hl < 4; hl++) {
                    sel[hl] += __shfl_xor_sync(0xffffffffu, sel[hl], 1);
                    sel[hl] += __shfl_xor_sync(0xffffffffu, sel[hl], 2);
                    ser[hl] += __shfl_xor_sync(0xffffffffu, ser[hl], 1);
                    ser[hl] += __shfl_xor_sync(0xffffffffu, ser[hl], 2);
                }
                if (r < M) {
#pragma unroll
                    for (int hl = 0; hl < 4; hl++)
                        if (hl == qid) {
                            gel[(size_t)r * H1 + wn * 4 + hl] = sel[hl];
                            ger[(size_t)r * H1 + wn * 4 + hl] = ser[hl];
                        }
                }
            }
    } else {
        // BN == 64: single head over 64 cols, spans both wn warps -> smem combine
        __shared__ float sEl[2][BM], sEr[2][BM];
        float wl[8], wr[8];
#pragma unroll
        for (int nt = 0; nt < 4; nt++) {
            int c = wn * 32 + nt * 8 + qid * 2;
            wl[nt * 2 + 0] = __ldg(attn_l + c);
            wl[nt * 2 + 1] = __ldg(attn_l + c + 1);
            wr[nt * 2 + 0] = __ldg(attn_r + c);
            wr[nt * 2 + 1] = __ldg(attn_r + c + 1);
        }
#pragma unroll
        for (int mt = 0; mt < 2; mt++)
#pragma unroll
            for (int hf = 0; hf < 2; hf++) {
                int lr = wm * 32 + mt * 16 + hf * 8 + gid;
                float sel = 0.f, ser = 0.f;
#pragma unroll
                for (int nt = 0; nt < 4; nt++) {
                    sel += acc[mt][nt][hf * 2] * wl[nt * 2] + acc[mt][nt][hf * 2 + 1] * wl[nt * 2 + 1];
                    ser += acc[mt][nt][hf * 2] * wr[nt * 2] + acc[mt][nt][hf * 2 + 1] * wr[nt * 2 + 1];
                }
                sel += __shfl_xor_sync(0xffffffffu, sel, 1);
                sel += __shfl_xor_sync(0xffffffffu, sel, 2);
                ser += __shfl_xor_sync(0xffffffffu, ser, 1);
                ser += __shfl_xor_sync(0xffffffffu, ser, 2);
                if (qid == 0) { sEl[wn][lr] = sel; sEr[wn][lr] = ser; }
            }
        __syncthreads();
        if (tid < BM) {
            int r = rowBase + tid;
            if (r < M) {
                gel[r] = sEl[0][tid] + sEl[1][tid];
                ger[r] = sEr[0][tid] + sEr[1][tid];
            }
        }
    }
}

// ---------------- layer1 fused softmax+aggregate: warp per dst node ----------------
__global__ void agg1_kernel(const float* __restrict__ bias1) {
    int t = blockIdx.x * blockDim.x + threadIdx.x;
    int w = t >> 5;
    if (w >= NN) return;
    int lane = t & 31;
    int h = lane >> 2;

    int beg = g_off[w], end = g_off[w + 1];
    float er_h = __ldg(g_er1 + (size_t)w * H1 + h);

    float acc0 = 0.f, acc1 = 0.f, acc2 = 0.f, acc3 = 0.f, ssum = 0.f;

    int i = beg;
    for (; i + 4 <= end; i += 4) {
        int s0 = __ldg(g_esrc + i + 0);
        int s1 = __ldg(g_esrc + i + 1);
        int s2 = __ldg(g_esrc + i + 2);
        int s3 = __ldg(g_esrc + i + 3);
        float el0 = __ldg(g_el1 + (size_t)s0 * H1 + h);
        float el1 = __ldg(g_el1 + (size_t)s1 * H1 + h);
        float el2 = __ldg(g_el1 + (size_t)s2 * H1 + h);
        float el3 = __ldg(g_el1 + (size_t)s3 * H1 + h);
        uint2 u0 = *reinterpret_cast<const uint2*>(g_feat1h + (size_t)s0 * F_HID + lane * 4);
        uint2 u1 = *reinterpret_cast<const uint2*>(g_feat1h + (size_t)s1 * F_HID + lane * 4);
        uint2 u2 = *reinterpret_cast<const uint2*>(g_feat1h + (size_t)s2 * F_HID + lane * 4);
        uint2 u3 = *reinterpret_cast<const uint2*>(g_feat1h + (size_t)s3 * F_HID + lane * 4);
        float p0 = __expf(leaky(el0 + er_h));
        float p1 = __expf(leaky(el1 + er_h));
        float p2 = __expf(leaky(el2 + er_h));
        float p3 = __expf(leaky(el3 + er_h));
        {
            float2 a = __half22float2(*reinterpret_cast<half2*>(&u0.x));
            float2 b = __half22float2(*reinterpret_cast<half2*>(&u0.y));
            acc0 = fmaf(p0, a.x, acc0); acc1 = fmaf(p0, a.y, acc1);
            acc2 = fmaf(p0, b.x, acc2); acc3 = fmaf(p0, b.y, acc3);
        }
        {
            float2 a = __half22float2(*reinterpret_cast<half2*>(&u1.x));
            float2 b = __half22float2(*reinterpret_cast<half2*>(&u1.y));
            acc0 = fmaf(p1, a.x, acc0); acc1 = fmaf(p1, a.y, acc1);
            acc2 = fmaf(p1, b.x, acc2); acc3 = fmaf(p1, b.y, acc3);
        }
        {
            float2 a = __half22float2(*reinterpret_cast<half2*>(&u2.x));
            float2 b = __half22float2(*reinterpret_cast<half2*>(&u2.y));
            acc0 = fmaf(p2, a.x, acc0); acc1 = fmaf(p2, a.y, acc1);
            acc2 = fmaf(p2, b.x, acc2); acc3 = fmaf(p2, b.y, acc3);
        }
        {
            float2 a = __half22float2(*reinterpret_cast<half2*>(&u3.x));
            float2 b = __half22float2(*reinterpret_cast<half2*>(&u3.y));
            acc0 = fmaf(p3, a.x, acc0); acc1 = fmaf(p3, a.y, acc1);
            acc2 = fmaf(p3, b.x, acc2); acc3 = fmaf(p3, b.y, acc3);
        }
        ssum += (p0 + p1) + (p2 + p3);
    }
    for (; i < end; i++) {
        int s = __ldg(g_esrc + i);
        float el = __ldg(g_el1 + (size_t)s * H1 + h);
        uint2 u = *reinterpret_cast<const uint2*>(g_feat1h + (size_t)s * F_HID + lane * 4);
        float p = __expf(leaky(el + er_h));
        float2 a = __half22float2(*reinterpret_cast<half2*>(&u.x));
        float2 b = __half22float2(*reinterpret_cast<half2*>(&u.y));
        acc0 = fmaf(p, a.x, acc0); acc1 = fmaf(p, a.y, acc1);
        acc2 = fmaf(p, b.x, acc2); acc3 = fmaf(p, b.y, acc3);
        ssum += p;
    }
    float inv = 1.f / fmaxf(ssum, 1e-9f);
    float4 b = *reinterpret_cast<const float4*>(bias1 + lane * 4);
    half2 o0 = __floats2half2_rn(acc0 * inv + b.x, acc1 * inv + b.y);
    half2 o1 = __floats2half2_rn(acc2 * inv + b.z, acc3 * inv + b.w);
    uint2 ou;
    ou.x = *reinterpret_cast<unsigned*>(&o0);
    ou.y = *reinterpret_cast<unsigned*>(&o1);
    *reinterpret_cast<uint2*>(g_h1h + (size_t)w * F_HID + lane * 4) = ou;
}

// ---------------- layer2 fused softmax+aggregate: warp per dst node (64 floats) -------------
__global__ void agg2_kernel(const float* __restrict__ bias2, float* __restrict__ out) {
    int t = blockIdx.x * blockDim.x + threadIdx.x;
    int w = t >> 5;
    if (w >= NN) return;
    int lane = t & 31;

    int beg = g_off[w], end = g_off[w + 1];
    float er = __ldg(g_er2 + w);

    float acc0 = 0.f, acc1 = 0.f, ssum = 0.f;

    int i = beg;
    for (; i + 4 <= end; i += 4) {
        int s0 = __ldg(g_esrc + i + 0);
        int s1 = __ldg(g_esrc + i + 1);
        int s2 = __ldg(g_esrc + i + 2);
        int s3 = __ldg(g_esrc + i + 3);
        float el0 = __ldg(g_el2 + s0);
        float el1 = __ldg(g_el2 + s1);
        float el2 = __ldg(g_el2 + s2);
        float el3 = __ldg(g_el2 + s3);
        unsigned u0 = *reinterpret_cast<const unsigned*>(g_feat2h + (size_t)s0 * F_OUT + lane * 2);
        unsigned u1 = *reinterpret_cast<const unsigned*>(g_feat2h + (size_t)s1 * F_OUT + lane * 2);
        unsigned u2 = *reinterpret_cast<const unsigned*>(g_feat2h + (size_t)s2 * F_OUT + lane * 2);
        unsigned u3 = *reinterpret_cast<const unsigned*>(g_feat2h + (size_t)s3 * F_OUT + lane * 2);
        float p0 = __expf(leaky(el0 + er));
        float p1 = __expf(leaky(el1 + er));
        float p2 = __expf(leaky(el2 + er));
        float p3 = __expf(leaky(el3 + er));
        float2 f0 = __half22float2(*reinterpret_cast<half2*>(&u0));
        float2 f1 = __half22float2(*reinterpret_cast<half2*>(&u1));
        float2 f2 = __half22float2(*reinterpret_cast<half2*>(&u2));
        float2 f3 = __half22float2(*reinterpret_cast<half2*>(&u3));
        acc0 = fmaf(p0, f0.x, acc0); acc1 = fmaf(p0, f0.y, acc1);
        acc0 = fmaf(p1, f1.x, acc0); acc1 = fmaf(p1, f1.y, acc1);
        acc0 = fmaf(p2, f2.x, acc0); acc1 = fmaf(p2, f2.y, acc1);
        acc0 = fmaf(p3, f3.x, acc0); acc1 = fmaf(p3, f3.y, acc1);
        ssum += (p0 + p1) + (p2 + p3);
    }
    for (; i < end; i++) {
        int s = __ldg(g_esrc + i);
        float el = __ldg(g_el2 + s);
        unsigned u = *reinterpret_cast<const unsigned*>(g_feat2h + (size_t)s * F_OUT + lane * 2);
        float p = __expf(leaky(el + er));
        float2 f = __half22float2(*reinterpret_cast<half2*>(&u));
        acc0 = fmaf(p, f.x, acc0); acc1 = fmaf(p, f.y, acc1);
        ssum += p;
    }
    float inv = 1.f / fmaxf(ssum, 1e-9f);
    float2 b = *reinterpret_cast<const float2*>(bias2 + lane * 2);
    float2 o = make_float2(acc0 * inv + b.x, acc1 * inv + b.y);
    *reinterpret_cast<float2*>(out + (size_t)w * F_OUT + lane * 2) = o;
}

// ---------------- launch ----------------
extern "C" void kernel_launch(void* const* d_in, const int* in_sizes, int n_in,
                              void* d_out, int out_size) {
    const float* x   = (const float*)d_in[0];
    const int*   src = (const int*)  d_in[1];
    const int*   dst = (const int*)  d_in[2];
    const float* W1  = (const float*)d_in[3];
    const float* al1 = (const float*)d_in[4];
    const float* ar1 = (const float*)d_in[5];
    const float* b1  = (const float*)d_in[6];
    const float* W2  = (const float*)d_in[7];
    const float* al2 = (const float*)d_in[8];
    const float* ar2 = (const float*)d_in[9];
    const float* b2  = (const float*)d_in[10];
    float* out = (float*)d_out;
    const int E = in_sizes[1];
    const int M = NN;

    __half *feat1h, *h1h, *feat2h;
    float *el1, *er1, *el2, *er2;
    cudaGetSymbolAddress((void**)&feat1h, g_feat1h);
    cudaGetSymbolAddress((void**)&h1h,    g_h1h);
    cudaGetSymbolAddress((void**)&feat2h, g_feat2h);
    cudaGetSymbolAddress((void**)&el1, g_el1);
    cudaGetSymbolAddress((void**)&er1, g_er1);
    cudaGetSymbolAddress((void**)&el2, g_el2);
    cudaGetSymbolAddress((void**)&er2, g_er2);

    static cudaStream_t s_side = nullptr;
    static cudaEvent_t  s_fork = nullptr, s_join = nullptr;
    if (!s_side) {
        cudaStreamCreateWithFlags(&s_side, cudaStreamNonBlocking);
        cudaEventCreateWithFlags(&s_fork, cudaEventDisableTiming);
        cudaEventCreateWithFlags(&s_join, cudaEventDisableTiming);
    }

    // fork: CSR build on side stream, concurrent with layer-1 GEMM
    cudaEventRecord(s_fork, 0);
    cudaStreamWaitEvent(s_side, s_fork, 0);
    init_kernel<<<(NN + 255) / 256, 256, 0, s_side>>>();
    hist_kernel<<<(E / 4 + 255) / 256, 256, 0, s_side>>>(dst, E);
    scan_kernel<<<1, 1024, 0, s_side>>>(E);
    scatter_kernel<<<(E / 4 + 255) / 256, 256, 0, s_side>>>(src, dst, E);
    cudaEventRecord(s_join, s_side);

    // main stream: layer-1 GEMM with fused elr + fp16 mirror
    hgemm_fused<F_HID, false, float><<<(M + 127) / 128, 256>>>(
        x, W1, feat1h, el1, er1, al1, ar1, M, F_IN);

    cudaStreamWaitEvent(0, s_join, 0);
    agg1_kernel<<<(NN * 32 + 255) / 256, 256>>>(b1);

    // layer 2: fp16 input (relu on load), fused elr
    hgemm_fused<F_OUT, true, __half><<<(M + 127) / 128, 256>>>(
        h1h, W2, feat2h, el2, er2, al2, ar2, M, F_HID);
    agg2_kernel<<<(NN * 32 + 255) / 256, 256>>>(b2, out);
}